// round 3
// baseline (speedup 1.0000x reference)
#include <cuda_runtime.h>
#include <cstddef>

// Problem dims
#define BB   16
#define NN   128
#define MMx  1024
#define DNx  512
#define DEx  256
#define WNC  128
#define WEC  128
#define PPx  512
#define HIDx 256

// ---------------- scratch (static __device__, no allocation) ----------------
__device__ float d_X    [BB*NN*DNx];     // masked node features      (2048 x 512)
__device__ float d_XWp  [BB*NN*256];     // [X@Wn | X@Wn2]            (2048 x 256)
__device__ float d_h    [BB*NN*WNC];     // relu(A @ XW)              (2048 x 128)
__device__ float d_Eg   [BB*MMx*DEx];    // gathered edge feats       (16384 x 256)
__device__ float d_EgWe [BB*MMx*WEC];    // Eg @ We                   (16384 x 128)
__device__ float d_g    [BB*MMx*WEC];    // relu(L @ EgWe)            (16384 x 128)
__device__ float d_agg  [BB*NN*WEC];     // scatter-add of g by src   (2048 x 128)
__device__ float d_EFp  [BB*PPx*DEx];    // edge feats at pairs       (8192 x 256)
__device__ float d_Qp   [BB*PPx*WEC];    // relu(EFp @ We2)           (8192 x 128)
__device__ float d_CI   [BB*PPx*512];    // classifier input          (8192 x 512)
__device__ float d_HID  [BB*PPx*768];    // 3-head hidden [lr|cr|mr]  (8192 x 768)
__device__ float d_Wncat[DNx*256];       // [Wn | Wn2]                (512 x 256)
__device__ float d_W1cat[512*768];       // [lrW1 | scrW1 | mrW1]     (512 x 768)
__device__ float d_b1cat[768];           // [lrb1 | scrb1 | mrb1]

// ---------------- generic SGEMM: 128x128 tile, BK=8, 8x8 microtile ----------
// C[M,N] = op(A[M,K] @ B[K,N] (+bias) (relu))   M%128==0, N%128==0, K%8==0
__global__ __launch_bounds__(256) void sgemm128(
    const float* __restrict__ A, int lda,
    const float* __restrict__ Bm, int ldb,
    float* __restrict__ C, int ldc,
    int K, const float* __restrict__ bias, int doRelu)
{
    __shared__ float As[8][128];
    __shared__ float Bs[8][128];
    const int tx   = threadIdx.x;            // 0..255
    const int row0 = blockIdx.y * 128;
    const int col0 = blockIdx.x * 128;
    const int tr   = tx >> 4;                // 0..15
    const int tc   = tx & 15;                // 0..15

    const int arow = tx >> 1;                // 0..127
    const int ak   = (tx & 1) * 4;           // 0 or 4
    const int brow = tx >> 5;                // 0..7
    const int bcol = (tx & 31) * 4;          // 0..124

    float acc[8][8];
    #pragma unroll
    for (int i = 0; i < 8; i++)
        #pragma unroll
        for (int j = 0; j < 8; j++) acc[i][j] = 0.f;

    for (int k0 = 0; k0 < K; k0 += 8) {
        float4 a = *(const float4*)&A[(size_t)(row0 + arow) * lda + k0 + ak];
        float4 b = *(const float4*)&Bm[(size_t)(k0 + brow) * ldb + col0 + bcol];
        __syncthreads();
        As[ak + 0][arow] = a.x; As[ak + 1][arow] = a.y;
        As[ak + 2][arow] = a.z; As[ak + 3][arow] = a.w;
        *(float4*)&Bs[brow][bcol] = b;
        __syncthreads();
        #pragma unroll
        for (int kk = 0; kk < 8; kk++) {
            float ar[8], br[8];
            #pragma unroll
            for (int i = 0; i < 8; i++) ar[i] = As[kk][tr * 8 + i];
            #pragma unroll
            for (int j = 0; j < 8; j++) br[j] = Bs[kk][tc * 8 + j];
            #pragma unroll
            for (int i = 0; i < 8; i++)
                #pragma unroll
                for (int j = 0; j < 8; j++)
                    acc[i][j] = fmaf(ar[i], br[j], acc[i][j]);
        }
    }

    #pragma unroll
    for (int i = 0; i < 8; i++) {
        int r = row0 + tr * 8 + i;
        #pragma unroll
        for (int j = 0; j < 8; j++) {
            int c = col0 + tc * 8 + j;
            float v = acc[i][j];
            if (bias) v += bias[c];
            if (doRelu) v = fmaxf(v, 0.f);
            C[(size_t)r * ldc + c] = v;
        }
    }
}

// ---------------- packing kernels -------------------------------------------
__global__ void pack_wn_kernel(const float* __restrict__ Wn,
                               const float* __restrict__ Wn2)
{
    int k = blockIdx.x, t = threadIdx.x;     // 512 blocks, 256 thr
    d_Wncat[k * 256 + t] = (t < 128) ? Wn[k * 128 + t] : Wn2[k * 128 + (t - 128)];
}

__global__ void pack_w1_kernel(const float* __restrict__ lrW1,  const float* __restrict__ lrb1,
                               const float* __restrict__ scrW1, const float* __restrict__ scrb1,
                               const float* __restrict__ mrW1,  const float* __restrict__ mrb1)
{
    int k = blockIdx.x, t = threadIdx.x;     // 512 blocks, 768 thr
    float v;
    if (t < 256)      v = lrW1 [k * 256 + t];
    else if (t < 512) v = scrW1[k * 256 + (t - 256)];
    else              v = mrW1 [k * 256 + (t - 512)];
    d_W1cat[k * 768 + t] = v;
    if (k == 0) {
        float b;
        if (t < 256)      b = lrb1 [t];
        else if (t < 512) b = scrb1[t - 256];
        else              b = mrb1 [t - 512];
        d_b1cat[t] = b;
    }
}

// ---------------- glue kernels ----------------------------------------------
__global__ void mask_x_kernel(const float* __restrict__ nf,
                              const int* __restrict__ num_obj)
{
    int blk = blockIdx.x;                // b*128+n, 2048 blocks, 128 thr
    int b = blk >> 7, n = blk & 127, t = threadIdx.x;
    float4 v = make_float4(0.f, 0.f, 0.f, 0.f);
    if (n < num_obj[b]) v = ((const float4*)nf)[(size_t)blk * 128 + t];
    ((float4*)d_X)[(size_t)blk * 128 + t] = v;
}

__global__ void gather_eg_kernel(const float* __restrict__ ef,
                                 const int* __restrict__ ei,
                                 const int* __restrict__ num_edges)
{
    int blk = blockIdx.x;                // b*1024+m, 16384 blocks, 64 thr
    int b = blk >> 10, m = blk & 1023, t = threadIdx.x;
    float4 v = make_float4(0.f, 0.f, 0.f, 0.f);
    if (m < num_edges[b]) {
        int s = ei[b * 2048 + m];
        int d = ei[b * 2048 + 1024 + m];
        v = ((const float4*)ef)[(((size_t)b * 128 + s) * 128 + d) * 64 + t];
    }
    ((float4*)d_Eg)[(size_t)blk * 64 + t] = v;
}

__global__ void adj_h_kernel(const float* __restrict__ adj,
                             const int* __restrict__ num_obj)
{
    int blk = blockIdx.x;                // b*128+i, 2048 blocks, 128 thr
    int b = blk >> 7, i = blk & 127, t = threadIdx.x;
    int no = num_obj[b];
    float* out = &d_h[(size_t)blk * 128];
    if (i >= no) { out[t] = 0.f; return; }
    __shared__ float arow[128];
    arow[t] = adj[(size_t)blk * 128 + t];
    __syncthreads();
    const float* xw = &d_XWp[(size_t)b * 128 * 256];   // XW part: cols [0,128)
    float acc = xw[i * 256 + t];                        // eye * nmask term
    for (int j = 0; j < no; ++j) {
        float w = arow[j];                              // block-uniform
        if (w != 0.f) acc = fmaf(w, xw[j * 256 + t], acc);
    }
    out[t] = fmaxf(acc, 0.f);
}

__global__ void line_g_kernel(const float* __restrict__ ladj,
                              const int* __restrict__ num_edges)
{
    int blk = blockIdx.x;                // b*1024+i, 16384 blocks, 128 thr
    int b = blk >> 10, i = blk & 1023, t = threadIdx.x;
    int ne = num_edges[b];
    float* out = &d_g[(size_t)blk * 128];
    if (i >= ne) { out[t] = 0.f; return; }

    __shared__ float lrow[1024];
    __shared__ int   jidx[1024];
    __shared__ float jw[1024];
    __shared__ int   cnt;
    if (t == 0) cnt = 0;
    const float* lp = &ladj[(size_t)blk * 1024];
    for (int j = t; j < 1024; j += 128) lrow[j] = lp[j];
    __syncthreads();
    for (int j = t; j < ne; j += 128) {
        float w = lrow[j];
        if (w != 0.f) { int p = atomicAdd(&cnt, 1); jidx[p] = j; jw[p] = w; }
    }
    __syncthreads();
    const float* ew = &d_EgWe[(size_t)b * 1024 * 128];
    float acc = ew[i * 128 + t];                     // eye * emask term
    int c = cnt;
    for (int k = 0; k < c; ++k)
        acc = fmaf(jw[k], ew[jidx[k] * 128 + t], acc);
    out[t] = fmaxf(acc, 0.f);
}

__global__ void zero_agg_kernel()
{
    d_agg[(size_t)blockIdx.x * 128 + threadIdx.x] = 0.f;
}

__global__ void agg_scatter_kernel(const int* __restrict__ ei,
                                   const int* __restrict__ num_edges)
{
    int blk = blockIdx.x;                // b*1024+m, 16384 blocks, 128 thr
    int b = blk >> 10, m = blk & 1023, t = threadIdx.x;
    if (m >= num_edges[b]) return;
    int s = ei[b * 2048 + m];
    float v = d_g[(size_t)blk * 128 + t];
    if (v != 0.f)
        atomicAdd(&d_agg[((size_t)b * 128 + s) * 128 + t], v);
}

__global__ void gather_ef_pair_kernel(const float* __restrict__ ef,
                                      const int* __restrict__ pairs)
{
    int blk = blockIdx.x;                // b*512+p, 8192 blocks, 64 thr
    int b = blk / 512, t = threadIdx.x;
    int p0 = pairs[blk * 2], p1 = pairs[blk * 2 + 1];
    ((float4*)d_EFp)[(size_t)blk * 64 + t] =
        ((const float4*)ef)[(((size_t)b * 128 + p0) * 128 + p1) * 64 + t];
}

__global__ void ci_kernel(const int* __restrict__ pairs,
                          const int* __restrict__ num_obj)
{
    int blk = blockIdx.x;                // b*512+p, 8192 blocks, 128 thr
    int b = blk / 512, t = threadIdx.x;
    int p0 = pairs[blk * 2], p1 = pairs[blk * 2 + 1];
    int no = num_obj[b];
    const float* hB = &d_h  [(size_t)b * 128 * 128];
    const float* aB = &d_agg[(size_t)b * 128 * 128];
    const float* xB = &d_XWp[(size_t)b * 128 * 256];   // Xp part: cols [128,256)
    float h0 = hB[p0 * 128 + t] + hB[p1 * 128 + t];
    float a0 = (p0 < no ? aB[p0 * 128 + t] : 0.f) +
               (p1 < no ? aB[p1 * 128 + t] : 0.f);
    float pm = fmaxf(xB[p0 * 256 + 128 + t] + xB[p1 * 256 + 128 + t], 0.f);
    float q  = d_Qp[(size_t)blk * 128 + t];            // already relu'ed
    float* ci = &d_CI[(size_t)blk * 512];
    ci[t]       = h0;
    ci[128 + t] = a0;
    ci[256 + t] = pm;
    ci[384 + t] = q;
}

__global__ void head_out_kernel(const float* __restrict__ lrW2, const float* __restrict__ lrb2,
                                const float* __restrict__ crW2, const float* __restrict__ crb2,
                                const float* __restrict__ mrW2, const float* __restrict__ mrb2,
                                float* __restrict__ out)
{
    int blk = blockIdx.x, t = threadIdx.x;  // 8192 blocks, 32 thr
    __shared__ float hid[768];
    const float* hr = &d_HID[(size_t)blk * 768];
    for (int i = t; i < 768; i += 32) hid[i] = hr[i];
    __syncwarp();

    int col, base, outd;
    const float *W2, *b2;
    float* op;
    if (t < 9)       { col = t;      base = 0;   outd = 9;  W2 = lrW2; b2 = lrb2; op = out + (size_t)blk * 9 + col; }
    else if (t < 15) { col = t - 9;  base = 256; outd = 6;  W2 = crW2; b2 = crb2; op = out + 73728 + (size_t)blk * 6 + col; }
    else if (t < 32) { col = t - 15; base = 512; outd = 17; W2 = mrW2; b2 = mrb2; op = out + 122880 + (size_t)blk * 17 + col; }
    else return;

    float acc = b2[col];
    for (int k = 0; k < 256; ++k)
        acc = fmaf(hid[base + k], W2[k * outd + col], acc);
    *op = acc;
}

// ---------------- launch -----------------------------------------------------
extern "C" void kernel_launch(void* const* d_in, const int* in_sizes, int n_in,
                              void* d_out, int out_size)
{
    const float* nf    = (const float*)d_in[0];
    const float* ef    = (const float*)d_in[1];
    const float* adj   = (const float*)d_in[2];
    const float* ladj  = (const float*)d_in[3];
    const int*   ei    = (const int*)  d_in[4];
    const int*   pairs = (const int*)  d_in[5];
    const int*   nobj  = (const int*)  d_in[6];
    const int*   nedg  = (const int*)  d_in[7];
    const float* Wn    = (const float*)d_in[8];
    const float* We    = (const float*)d_in[9];
    const float* Wn2   = (const float*)d_in[10];
    const float* We2   = (const float*)d_in[11];
    const float* scrW1 = (const float*)d_in[12];
    const float* scrb1 = (const float*)d_in[13];
    const float* scrW2 = (const float*)d_in[14];
    const float* scrb2 = (const float*)d_in[15];
    const float* lrW1  = (const float*)d_in[16];
    const float* lrb1  = (const float*)d_in[17];
    const float* lrW2  = (const float*)d_in[18];
    const float* lrb2  = (const float*)d_in[19];
    const float* mrW1  = (const float*)d_in[20];
    const float* mrb1  = (const float*)d_in[21];
    const float* mrW2  = (const float*)d_in[22];
    const float* mrb2  = (const float*)d_in[23];
    float* out = (float*)d_out;

    float *pX, *pXWp, *pEg, *pEgWe, *pEFp, *pQp, *pCI, *pHID, *pWncat, *pW1cat, *pb1cat;
    cudaGetSymbolAddress((void**)&pX,     d_X);
    cudaGetSymbolAddress((void**)&pXWp,   d_XWp);
    cudaGetSymbolAddress((void**)&pEg,    d_Eg);
    cudaGetSymbolAddress((void**)&pEgWe,  d_EgWe);
    cudaGetSymbolAddress((void**)&pEFp,   d_EFp);
    cudaGetSymbolAddress((void**)&pQp,    d_Qp);
    cudaGetSymbolAddress((void**)&pCI,    d_CI);
    cudaGetSymbolAddress((void**)&pHID,   d_HID);
    cudaGetSymbolAddress((void**)&pWncat, d_Wncat);
    cudaGetSymbolAddress((void**)&pW1cat, d_W1cat);
    cudaGetSymbolAddress((void**)&pb1cat, d_b1cat);

    // 0. weight packing (cheap, deterministic each call)
    pack_wn_kernel<<<512, 256>>>(Wn, Wn2);
    pack_w1_kernel<<<512, 768>>>(lrW1, lrb1, scrW1, scrb1, mrW1, mrb1);
    // 1. masked X
    mask_x_kernel<<<2048, 128>>>(nf, nobj);
    // 2. [XW | Xp] = X @ [Wn | Wn2]
    sgemm128<<<dim3(2, 16), 256>>>(pX, DNx, pWncat, 256, pXWp, 256, DNx, nullptr, 0);
    // 3. Eg gather + EgWe = Eg @ We
    gather_eg_kernel<<<16384, 64>>>(ef, ei, nedg);
    sgemm128<<<dim3(1, 128), 256>>>(pEg, DEx, We, WEC, pEgWe, WEC, DEx, nullptr, 0);
    // 4. h = relu(A @ XW) * nmask
    adj_h_kernel<<<2048, 128>>>(adj, nobj);
    // 5. g = relu(L @ EgWe) * emask  (sparse row compaction)
    line_g_kernel<<<16384, 128>>>(ladj, nedg);
    // 6. agg = scatter_add(g, src)
    zero_agg_kernel<<<2048, 128>>>();
    agg_scatter_kernel<<<16384, 128>>>(ei, nedg);
    // 7. pair edge features + Q = relu(EFp @ We2)
    gather_ef_pair_kernel<<<8192, 64>>>(ef, pairs);
    sgemm128<<<dim3(1, 64), 256>>>(pEFp, DEx, We2, WEC, pQp, WEC, DEx, nullptr, 1);
    // 8. assemble CI = [h0+h1 | agg0+agg1 | relu(Xp0+Xp1) | Q]
    ci_kernel<<<8192, 128>>>(pairs, nobj);
    // 9. hidden = relu(CI @ [lrW1|scrW1|mrW1] + b1cat)  -> d_HID
    sgemm128<<<dim3(6, 64), 256>>>(pCI, 512, pW1cat, 768, pHID, 768, 512, pb1cat, 1);
    // 10. heads -> out  (lr | cr | mr)
    head_out_kernel<<<8192, 32>>>(lrW2, lrb2, scrW2, scrb2, mrW2, mrb2, out);
}

// round 4
// speedup vs baseline: 1.3952x; 1.3952x over previous
#include <cuda_runtime.h>
#include <cstddef>
#include <cstdint>

// Problem dims
#define BB   16
#define NN   128
#define MMx  1024
#define DNx  512
#define DEx  256
#define WNC  128
#define WEC  128
#define PPx  512
#define HIDx 256

// ---------------- scratch (static __device__, no allocation) ----------------
__device__ float d_X    [BB*NN*DNx];     // masked node features      (2048 x 512)
__device__ float d_XWp  [BB*NN*256];     // [X@Wn | X@Wn2]            (2048 x 256)
__device__ float d_h    [BB*NN*WNC];     // relu(A @ XW)              (2048 x 128)
__device__ float d_Eg   [BB*MMx*DEx];    // gathered edge feats       (16384 x 256)
__device__ float d_EgWe [BB*MMx*WEC];    // Eg @ We                   (16384 x 128)
__device__ float d_g    [BB*MMx*WEC];    // relu(L @ EgWe)            (16384 x 128)
__device__ float d_agg  [BB*NN*WEC];     // scatter-add of g by src   (2048 x 128)
__device__ float d_EFp  [BB*PPx*DEx];    // edge feats at pairs       (8192 x 256)
__device__ float d_Qp   [BB*PPx*WEC];    // relu(EFp @ We2)           (8192 x 128)
__device__ float d_CI   [BB*PPx*512];    // classifier input          (8192 x 512)
__device__ float d_HID  [BB*PPx*768];    // 3-head hidden [lr|cr|mr]  (8192 x 768)
__device__ float d_Wncat[DNx*256];       // [Wn | Wn2]                (512 x 256)
__device__ float d_W1cat[512*768];       // [lrW1 | scrW1 | mrW1]     (512 x 768)
__device__ float d_b1cat[768];           // [lrb1 | scrb1 | mrb1]

// ---------------- tf32 warp-MMA GEMM ----------------------------------------
// C[M,N] = op(A[M,K] @ B[K,N] (+bias) (relu))
// M%128==0, N%128==0, K%16==0. A split hi+lo (compensated tf32), B tf32-rna.
// 256 threads, tile 128x128, BK=16; warp grid 4 (rows) x 2 (cols), each warp
// computes 32x64 via m16n8k8: 2 m-tiles x 8 n-tiles.

__device__ __forceinline__ uint32_t f2tf(float x) {
    uint32_t r; asm("cvt.rna.tf32.f32 %0, %1;" : "=r"(r) : "f"(x)); return r;
}

__device__ __forceinline__ void mma_tf32(float c[4], const uint32_t a[4], const uint32_t b[2]) {
    asm volatile(
        "mma.sync.aligned.m16n8k8.row.col.f32.tf32.tf32.f32 "
        "{%0,%1,%2,%3}, {%4,%5,%6,%7}, {%8,%9}, {%0,%1,%2,%3};\n"
        : "+f"(c[0]), "+f"(c[1]), "+f"(c[2]), "+f"(c[3])
        : "r"(a[0]), "r"(a[1]), "r"(a[2]), "r"(a[3]), "r"(b[0]), "r"(b[1]));
}

#define AST 20    // As row stride (elems): 20g mod 32 distinct over g<8 -> conflict-free
#define BST 136   // Bs k-row stride: 136t mod 32 = 8t -> conflict-free

__global__ __launch_bounds__(256) void mma_gemm(
    const float* __restrict__ A, int lda,
    const float* __restrict__ B, int ldb,
    float* __restrict__ C, int ldc,
    int K, const float* __restrict__ bias, int doRelu)
{
    __shared__ uint32_t AsHi[128 * AST];
    __shared__ uint32_t AsLo[128 * AST];
    __shared__ uint32_t Bs  [16 * BST];

    const int tx   = threadIdx.x;
    const int row0 = blockIdx.y * 128;
    const int col0 = blockIdx.x * 128;
    const int w    = tx >> 5, lane = tx & 31;
    const int wr   = w & 3,  wc   = w >> 2;     // 4 row-warps x 2 col-warps
    const int g    = lane >> 2, t = lane & 3;

    // smem-fill mapping
    const int ar  = tx >> 1, akc = (tx & 1) * 8;   // A: row 0..127, k-chunk 0/8
    const int bkr = tx >> 4, bnc = (tx & 15) * 8;  // B: k-row 0..15, n-chunk

    const float* Aptr = A + (size_t)(row0 + ar) * lda + akc;
    const float* Bptr = B + (size_t)bkr * ldb + col0 + bnc;

    float c[2][8][4];
    #pragma unroll
    for (int mt = 0; mt < 2; mt++)
        #pragma unroll
        for (int nt = 0; nt < 8; nt++)
            #pragma unroll
            for (int i = 0; i < 4; i++) c[mt][nt][i] = 0.f;

    // initial prefetch
    float4 fa0 = *(const float4*)(Aptr);
    float4 fa1 = *(const float4*)(Aptr + 4);
    float4 fb0 = *(const float4*)(Bptr);
    float4 fb1 = *(const float4*)(Bptr + 4);

    for (int k0 = 0; k0 < K; k0 += 16) {
        __syncthreads();   // previous tile's compute done
        {
            const float* pa = &fa0.x;
            #pragma unroll
            for (int j = 0; j < 4; j++) {
                float x = pa[j];
                uint32_t hi = f2tf(x);
                AsHi[ar * AST + akc + j] = hi;
                AsLo[ar * AST + akc + j] = f2tf(x - __uint_as_float(hi));
            }
            const float* pb = &fa1.x;
            #pragma unroll
            for (int j = 0; j < 4; j++) {
                float x = pb[j];
                uint32_t hi = f2tf(x);
                AsHi[ar * AST + akc + 4 + j] = hi;
                AsLo[ar * AST + akc + 4 + j] = f2tf(x - __uint_as_float(hi));
            }
            const float* qb0 = &fb0.x;
            const float* qb1 = &fb1.x;
            #pragma unroll
            for (int j = 0; j < 4; j++) Bs[bkr * BST + bnc + j]     = f2tf(qb0[j]);
            #pragma unroll
            for (int j = 0; j < 4; j++) Bs[bkr * BST + bnc + 4 + j] = f2tf(qb1[j]);
        }
        __syncthreads();

        if (k0 + 16 < K) {   // prefetch next tile while computing this one
            fa0 = *(const float4*)(Aptr + k0 + 16);
            fa1 = *(const float4*)(Aptr + k0 + 20);
            fb0 = *(const float4*)(Bptr + (size_t)(k0 + 16) * ldb);
            fb1 = *(const float4*)(Bptr + (size_t)(k0 + 16) * ldb + 4);
        }

        #pragma unroll
        for (int kk = 0; kk < 16; kk += 8) {
            uint32_t ah[2][4], al[2][4], bb[8][2];
            #pragma unroll
            for (int mt = 0; mt < 2; mt++) {
                int rb = (wr * 32 + mt * 16 + g) * AST + kk + t;
                int rb8 = rb + 8 * AST;
                ah[mt][0] = AsHi[rb];      ah[mt][1] = AsHi[rb8];
                ah[mt][2] = AsHi[rb + 4];  ah[mt][3] = AsHi[rb8 + 4];
                al[mt][0] = AsLo[rb];      al[mt][1] = AsLo[rb8];
                al[mt][2] = AsLo[rb + 4];  al[mt][3] = AsLo[rb8 + 4];
            }
            #pragma unroll
            for (int nt = 0; nt < 8; nt++) {
                int cb = (kk + t) * BST + wc * 64 + nt * 8 + g;
                bb[nt][0] = Bs[cb];
                bb[nt][1] = Bs[cb + 4 * BST];
            }
            #pragma unroll
            for (int mt = 0; mt < 2; mt++)
                #pragma unroll
                for (int nt = 0; nt < 8; nt++) {
                    mma_tf32(c[mt][nt], ah[mt], bb[nt]);
                    mma_tf32(c[mt][nt], al[mt], bb[nt]);
                }
        }
    }

    // epilogue
    #pragma unroll
    for (int mt = 0; mt < 2; mt++) {
        int r  = row0 + wr * 32 + mt * 16 + g;
        #pragma unroll
        for (int nt = 0; nt < 8; nt++) {
            int cc = col0 + wc * 64 + nt * 8 + 2 * t;
            float b0 = bias ? bias[cc]     : 0.f;
            float b1 = bias ? bias[cc + 1] : 0.f;
            float v0 = c[mt][nt][0] + b0, v1 = c[mt][nt][1] + b1;
            float v2 = c[mt][nt][2] + b0, v3 = c[mt][nt][3] + b1;
            if (doRelu) {
                v0 = fmaxf(v0, 0.f); v1 = fmaxf(v1, 0.f);
                v2 = fmaxf(v2, 0.f); v3 = fmaxf(v3, 0.f);
            }
            C[(size_t)r * ldc + cc]           = v0;
            C[(size_t)r * ldc + cc + 1]       = v1;
            C[(size_t)(r + 8) * ldc + cc]     = v2;
            C[(size_t)(r + 8) * ldc + cc + 1] = v3;
        }
    }
}

// ---------------- packing kernels -------------------------------------------
__global__ void pack_wn_kernel(const float* __restrict__ Wn,
                               const float* __restrict__ Wn2)
{
    int k = blockIdx.x, t = threadIdx.x;     // 512 blocks, 256 thr
    d_Wncat[k * 256 + t] = (t < 128) ? Wn[k * 128 + t] : Wn2[k * 128 + (t - 128)];
}

__global__ void pack_w1_kernel(const float* __restrict__ lrW1,  const float* __restrict__ lrb1,
                               const float* __restrict__ scrW1, const float* __restrict__ scrb1,
                               const float* __restrict__ mrW1,  const float* __restrict__ mrb1)
{
    int k = blockIdx.x, t = threadIdx.x;     // 512 blocks, 768 thr
    float v;
    if (t < 256)      v = lrW1 [k * 256 + t];
    else if (t < 512) v = scrW1[k * 256 + (t - 256)];
    else              v = mrW1 [k * 256 + (t - 512)];
    d_W1cat[k * 768 + t] = v;
    if (k == 0) {
        float b;
        if (t < 256)      b = lrb1 [t];
        else if (t < 512) b = scrb1[t - 256];
        else              b = mrb1 [t - 512];
        d_b1cat[t] = b;
    }
}

// ---------------- glue kernels ----------------------------------------------
__global__ void mask_x_kernel(const float* __restrict__ nf,
                              const int* __restrict__ num_obj)
{
    int blk = blockIdx.x;                // b*128+n, 2048 blocks, 128 thr
    int b = blk >> 7, n = blk & 127, t = threadIdx.x;
    float4 v = make_float4(0.f, 0.f, 0.f, 0.f);
    if (n < num_obj[b]) v = ((const float4*)nf)[(size_t)blk * 128 + t];
    ((float4*)d_X)[(size_t)blk * 128 + t] = v;
}

__global__ void gather_eg_kernel(const float* __restrict__ ef,
                                 const int* __restrict__ ei,
                                 const int* __restrict__ num_edges)
{
    int blk = blockIdx.x;                // b*1024+m, 16384 blocks, 64 thr
    int b = blk >> 10, m = blk & 1023, t = threadIdx.x;
    float4 v = make_float4(0.f, 0.f, 0.f, 0.f);
    if (m < num_edges[b]) {
        int s = ei[b * 2048 + m];
        int d = ei[b * 2048 + 1024 + m];
        v = ((const float4*)ef)[(((size_t)b * 128 + s) * 128 + d) * 64 + t];
    }
    ((float4*)d_Eg)[(size_t)blk * 64 + t] = v;
}

__global__ void adj_h_kernel(const float* __restrict__ adj,
                             const int* __restrict__ num_obj)
{
    int blk = blockIdx.x;                // b*128+i, 2048 blocks, 128 thr
    int b = blk >> 7, i = blk & 127, t = threadIdx.x;
    int no = num_obj[b];
    float* out = &d_h[(size_t)blk * 128];
    if (i >= no) { out[t] = 0.f; return; }
    __shared__ float arow[128];
    arow[t] = adj[(size_t)blk * 128 + t];
    __syncthreads();
    const float* xw = &d_XWp[(size_t)b * 128 * 256];   // XW part: cols [0,128)
    float acc = xw[i * 256 + t];                        // eye * nmask term
    for (int j = 0; j < no; ++j) {
        float w = arow[j];                              // block-uniform
        if (w != 0.f) acc = fmaf(w, xw[j * 256 + t], acc);
    }
    out[t] = fmaxf(acc, 0.f);
}

__global__ void line_g_kernel(const float* __restrict__ ladj,
                              const int* __restrict__ num_edges)
{
    int blk = blockIdx.x;                // b*1024+i, 16384 blocks, 128 thr
    int b = blk >> 10, i = blk & 1023, t = threadIdx.x;
    int ne = num_edges[b];
    float* out = &d_g[(size_t)blk * 128];
    if (i >= ne) { out[t] = 0.f; return; }

    __shared__ float lrow[1024];
    __shared__ int   jidx[1024];
    __shared__ float jw[1024];
    __shared__ int   cnt;
    if (t == 0) cnt = 0;
    const float* lp = &ladj[(size_t)blk * 1024];
    for (int j = t; j < 1024; j += 128) lrow[j] = lp[j];
    __syncthreads();
    for (int j = t; j < ne; j += 128) {
        float w = lrow[j];
        if (w != 0.f) { int p = atomicAdd(&cnt, 1); jidx[p] = j; jw[p] = w; }
    }
    __syncthreads();
    const float* ew = &d_EgWe[(size_t)b * 1024 * 128];
    float acc = ew[i * 128 + t];                     // eye * emask term
    int c = cnt;
    for (int k = 0; k < c; ++k)
        acc = fmaf(jw[k], ew[jidx[k] * 128 + t], acc);
    out[t] = fmaxf(acc, 0.f);
}

__global__ void zero_agg_kernel()
{
    d_agg[(size_t)blockIdx.x * 128 + threadIdx.x] = 0.f;
}

__global__ void agg_scatter_kernel(const int* __restrict__ ei,
                                   const int* __restrict__ num_edges)
{
    int blk = blockIdx.x;                // b*1024+m, 16384 blocks, 128 thr
    int b = blk >> 10, m = blk & 1023, t = threadIdx.x;
    if (m >= num_edges[b]) return;
    int s = ei[b * 2048 + m];
    float v = d_g[(size_t)blk * 128 + t];
    if (v != 0.f)
        atomicAdd(&d_agg[((size_t)b * 128 + s) * 128 + t], v);
}

__global__ void gather_ef_pair_kernel(const float* __restrict__ ef,
                                      const int* __restrict__ pairs)
{
    int blk = blockIdx.x;                // b*512+p, 8192 blocks, 64 thr
    int b = blk / 512, t = threadIdx.x;
    int p0 = pairs[blk * 2], p1 = pairs[blk * 2 + 1];
    ((float4*)d_EFp)[(size_t)blk * 64 + t] =
        ((const float4*)ef)[(((size_t)b * 128 + p0) * 128 + p1) * 64 + t];
}

__global__ void ci_kernel(const int* __restrict__ pairs,
                          const int* __restrict__ num_obj)
{
    int blk = blockIdx.x;                // b*512+p, 8192 blocks, 128 thr
    int b = blk / 512, t = threadIdx.x;
    int p0 = pairs[blk * 2], p1 = pairs[blk * 2 + 1];
    int no = num_obj[b];
    const float* hB = &d_h  [(size_t)b * 128 * 128];
    const float* aB = &d_agg[(size_t)b * 128 * 128];
    const float* xB = &d_XWp[(size_t)b * 128 * 256];   // Xp part: cols [128,256)
    float h0 = hB[p0 * 128 + t] + hB[p1 * 128 + t];
    float a0 = (p0 < no ? aB[p0 * 128 + t] : 0.f) +
               (p1 < no ? aB[p1 * 128 + t] : 0.f);
    float pm = fmaxf(xB[p0 * 256 + 128 + t] + xB[p1 * 256 + 128 + t], 0.f);
    float q  = d_Qp[(size_t)blk * 128 + t];            // already relu'ed
    float* ci = &d_CI[(size_t)blk * 512];
    ci[t]       = h0;
    ci[128 + t] = a0;
    ci[256 + t] = pm;
    ci[384 + t] = q;
}

__global__ void head_out_kernel(const float* __restrict__ lrW2, const float* __restrict__ lrb2,
                                const float* __restrict__ crW2, const float* __restrict__ crb2,
                                const float* __restrict__ mrW2, const float* __restrict__ mrb2,
                                float* __restrict__ out)
{
    int blk = blockIdx.x, t = threadIdx.x;  // 8192 blocks, 32 thr
    __shared__ float hid[768];
    const float* hr = &d_HID[(size_t)blk * 768];
    for (int i = t; i < 768; i += 32) hid[i] = hr[i];
    __syncwarp();

    int col, base, outd;
    const float *W2, *b2;
    float* op;
    if (t < 9)       { col = t;      base = 0;   outd = 9;  W2 = lrW2; b2 = lrb2; op = out + (size_t)blk * 9 + col; }
    else if (t < 15) { col = t - 9;  base = 256; outd = 6;  W2 = crW2; b2 = crb2; op = out + 73728 + (size_t)blk * 6 + col; }
    else if (t < 32) { col = t - 15; base = 512; outd = 17; W2 = mrW2; b2 = mrb2; op = out + 122880 + (size_t)blk * 17 + col; }
    else return;

    float acc = b2[col];
    for (int k = 0; k < 256; ++k)
        acc = fmaf(hid[base + k], W2[k * outd + col], acc);
    *op = acc;
}

// ---------------- launch -----------------------------------------------------
extern "C" void kernel_launch(void* const* d_in, const int* in_sizes, int n_in,
                              void* d_out, int out_size)
{
    const float* nf    = (const float*)d_in[0];
    const float* ef    = (const float*)d_in[1];
    const float* adj   = (const float*)d_in[2];
    const float* ladj  = (const float*)d_in[3];
    const int*   ei    = (const int*)  d_in[4];
    const int*   pairs = (const int*)  d_in[5];
    const int*   nobj  = (const int*)  d_in[6];
    const int*   nedg  = (const int*)  d_in[7];
    const float* Wn    = (const float*)d_in[8];
    const float* We    = (const float*)d_in[9];
    const float* Wn2   = (const float*)d_in[10];
    const float* We2   = (const float*)d_in[11];
    const float* scrW1 = (const float*)d_in[12];
    const float* scrb1 = (const float*)d_in[13];
    const float* scrW2 = (const float*)d_in[14];
    const float* scrb2 = (const float*)d_in[15];
    const float* lrW1  = (const float*)d_in[16];
    const float* lrb1  = (const float*)d_in[17];
    const float* lrW2  = (const float*)d_in[18];
    const float* lrb2  = (const float*)d_in[19];
    const float* mrW1  = (const float*)d_in[20];
    const float* mrb1  = (const float*)d_in[21];
    const float* mrW2  = (const float*)d_in[22];
    const float* mrb2  = (const float*)d_in[23];
    float* out = (float*)d_out;

    float *pX, *pXWp, *pEg, *pEgWe, *pEFp, *pQp, *pCI, *pHID, *pWncat, *pW1cat, *pb1cat;
    cudaGetSymbolAddress((void**)&pX,     d_X);
    cudaGetSymbolAddress((void**)&pXWp,   d_XWp);
    cudaGetSymbolAddress((void**)&pEg,    d_Eg);
    cudaGetSymbolAddress((void**)&pEgWe,  d_EgWe);
    cudaGetSymbolAddress((void**)&pEFp,   d_EFp);
    cudaGetSymbolAddress((void**)&pQp,    d_Qp);
    cudaGetSymbolAddress((void**)&pCI,    d_CI);
    cudaGetSymbolAddress((void**)&pHID,   d_HID);
    cudaGetSymbolAddress((void**)&pWncat, d_Wncat);
    cudaGetSymbolAddress((void**)&pW1cat, d_W1cat);
    cudaGetSymbolAddress((void**)&pb1cat, d_b1cat);

    // 0. weight packing (cheap, deterministic each call)
    pack_wn_kernel<<<512, 256>>>(Wn, Wn2);
    pack_w1_kernel<<<512, 768>>>(lrW1, lrb1, scrW1, scrb1, mrW1, mrb1);
    // 1. masked X
    mask_x_kernel<<<2048, 128>>>(nf, nobj);
    // 2. [XW | Xp] = X @ [Wn | Wn2]
    mma_gemm<<<dim3(2, 16), 256>>>(pX, DNx, pWncat, 256, pXWp, 256, DNx, nullptr, 0);
    // 3. Eg gather + EgWe = Eg @ We
    gather_eg_kernel<<<16384, 64>>>(ef, ei, nedg);
    mma_gemm<<<dim3(1, 128), 256>>>(pEg, DEx, We, WEC, pEgWe, WEC, DEx, nullptr, 0);
    // 4. h = relu(A @ XW) * nmask
    adj_h_kernel<<<2048, 128>>>(adj, nobj);
    // 5. g = relu(L @ EgWe) * emask  (sparse row compaction)
    line_g_kernel<<<16384, 128>>>(ladj, nedg);
    // 6. agg = scatter_add(g, src)
    zero_agg_kernel<<<2048, 128>>>();
    agg_scatter_kernel<<<16384, 128>>>(ei, nedg);
    // 7. pair edge features + Q = relu(EFp @ We2)
    gather_ef_pair_kernel<<<8192, 64>>>(ef, pairs);
    mma_gemm<<<dim3(1, 64), 256>>>(pEFp, DEx, We2, WEC, pQp, WEC, DEx, nullptr, 1);
    // 8. assemble CI = [h0+h1 | agg0+agg1 | relu(Xp0+Xp1) | Q]
    ci_kernel<<<8192, 128>>>(pairs, nobj);
    // 9. hidden = relu(CI @ [lrW1|scrW1|mrW1] + b1cat)  -> d_HID
    mma_gemm<<<dim3(6, 64), 256>>>(pCI, 512, pW1cat, 768, pHID, 768, 512, pb1cat, 1);
    // 10. heads -> out  (lr | cr | mr)
    head_out_kernel<<<8192, 32>>>(lrW2, lrb2, scrW2, scrb2, mrW2, mrb2, out);
}

// round 6
// speedup vs baseline: 2.1478x; 1.5394x over previous
#include <cuda_runtime.h>
#include <cuda_bf16.h>
#include <cstdint>
#include <cstddef>

// Problem dims
#define BB   16
#define NN   128
#define MMx  1024
#define DNx  512
#define DEx  256
#define PPx  512

// ---------------- scratch (static __device__, no allocation) ----------------
__device__ __nv_bfloat16 d_Xhi [BB*NN*DNx],  d_Xlo [BB*NN*DNx];   // 2048x512
__device__ float         d_XWp [BB*NN*256];                        // [XW|Xp]
__device__ float         d_h   [BB*NN*128];
__device__ __nv_bfloat16 d_Eghi[BB*MMx*DEx], d_Eglo[BB*MMx*DEx];  // 16384x256
__device__ float         d_EgWe[BB*MMx*128];
__device__ float         d_g   [BB*MMx*128];
__device__ float         d_agg [BB*NN*128];
__device__ __nv_bfloat16 d_EFphi[BB*PPx*DEx], d_EFplo[BB*PPx*DEx];// 8192x256
__device__ float         d_Qp  [BB*PPx*128];
__device__ __nv_bfloat16 d_CIhi[BB*PPx*512], d_CIlo[BB*PPx*512];  // 8192x512
__device__ float         d_HID [BB*PPx*768];
// transposed + split weights: [N][K] K-major
__device__ __nv_bfloat16 d_WtXWhi[256*512], d_WtXWlo[256*512];
__device__ __nv_bfloat16 d_WtEghi[128*256], d_WtEglo[128*256];
__device__ __nv_bfloat16 d_WtQhi [128*256], d_WtQlo [128*256];
__device__ __nv_bfloat16 d_WtW1hi[768*512], d_WtW1lo[768*512];
__device__ float         d_b1cat[768];

// ---------------- asm helpers ------------------------------------------------
__device__ __forceinline__ uint32_t smem_u32(const void* p) {
    uint32_t a;
    asm("{ .reg .u64 t; cvta.to.shared.u64 t, %1; cvt.u32.u64 %0, t; }" : "=r"(a) : "l"(p));
    return a;
}
#define CP16(sa, ga) \
    asm volatile("cp.async.cg.shared.global [%0], [%1], 16;" :: "r"(sa), "l"(ga))
#define CP_COMMIT() asm volatile("cp.async.commit_group;" ::: "memory")
#define CP_WAIT(n)  asm volatile("cp.async.wait_group %0;" :: "n"(n) : "memory")

#define LDSM4(r, a) \
    asm volatile("ldmatrix.sync.aligned.m8n8.x4.shared.b16 {%0,%1,%2,%3}, [%4];" \
        : "=r"((r)[0]), "=r"((r)[1]), "=r"((r)[2]), "=r"((r)[3]) : "r"(a))

#define MMA16816(c, a, b0, b1) \
    asm volatile("mma.sync.aligned.m16n8k16.row.col.f32.bf16.bf16.f32 " \
        "{%0,%1,%2,%3},{%4,%5,%6,%7},{%8,%9},{%0,%1,%2,%3};" \
        : "+f"((c)[0]), "+f"((c)[1]), "+f"((c)[2]), "+f"((c)[3]) \
        : "r"((a)[0]), "r"((a)[1]), "r"((a)[2]), "r"((a)[3]), "r"(b0), "r"(b1))

// ---------------- batched bf16 tensor-core GEMM ------------------------------
// C[M,N] = op(A @ B^T (+bias) (relu)); A[M,K] hi/lo bf16 K-major;
// B[Ntot,K] hi/lo bf16 K-major (pre-transposed). K % 32 == 0.
// Tile 128x128, BK=32, 8 warps (4 row x 2 col), warp tile 32x64, m16n8k16.
// 3-term compensated: AhiBhi + AloBhi + AhiBlo.
struct Gd {
    const __nv_bfloat16 *Ahi, *Alo, *Bhi, *Blo;
    float* C; const float* bias;
    int ldc, K, tilesX, blkEnd, doRelu, pad;
};
struct Gp { Gd d[3]; int n; };

#define S_AHI 0
#define S_ALO 8192
#define S_BHI 16384
#define S_BLO 24576
#define STG   32768
#define GEMM_SMEM (2 * STG)   // 64 KB

// swizzled byte offset of 16B chunk c (0..3) in row r (row = 64B)
__device__ __forceinline__ uint32_t swz(int r, int c) {
    return (uint32_t)(r * 64 + ((c ^ ((r >> 1) & 3)) << 4));
}

__global__ __launch_bounds__(256, 2) void gemm_batch(Gp gp)
{
    extern __shared__ char smem[];
    const uint32_t sb = smem_u32(smem);

    int bid = blockIdx.x, di = 0;
    while (di < gp.n - 1 && bid >= gp.d[di].blkEnd) di++;
    const Gd g = gp.d[di];
    const int base  = di ? gp.d[di - 1].blkEnd : 0;
    const int local = bid - base;
    const int row0  = (local / g.tilesX) * 128;
    const int col0  = (local % g.tilesX) * 128;
    const int K     = g.K;
    const int nT    = K >> 5;

    const int tid = threadIdx.x, lane = tid & 31, wid = tid >> 5;
    const int wr = wid & 3, wc = wid >> 2;

    // fill mapping: thread -> row r=tid>>1, chunks {c0, c0+1}
    const int fr = tid >> 1, fc0 = (tid & 1) * 2;
    const char* gAhi = (const char*)g.Ahi + ((size_t)(row0 + fr) * K) * 2;
    const char* gAlo = (const char*)g.Alo + ((size_t)(row0 + fr) * K) * 2;
    const char* gBhi = (const char*)g.Bhi + ((size_t)(col0 + fr) * K) * 2;
    const char* gBlo = (const char*)g.Blo + ((size_t)(col0 + fr) * K) * 2;

    float c[2][8][4];
    #pragma unroll
    for (int mt = 0; mt < 2; mt++)
        #pragma unroll
        for (int nt = 0; nt < 8; nt++)
            #pragma unroll
            for (int i = 0; i < 4; i++) c[mt][nt][i] = 0.f;

    // precomputed ldmatrix relative offsets
    //  A: mats {m@kk, m+8@kk, m@kk+8, m+8@kk+8}
    const int arow = wr * 32 + (lane & 7) + (lane & 8);
    const int acs  = (lane & 16) ? 1 : 0;
    //  B: mats {n@kk, n@kk+8, n+8@kk, n+8@kk+8}
    const int brow0 = wc * 64 + (lane & 7) + ((lane & 16) ? 8 : 0);
    const int bcs   = (lane & 8) ? 1 : 0;

    // prologue: load tile 0 into stage 0
    {
        const size_t kb = 0;
        #pragma unroll
        for (int c2 = 0; c2 < 2; c2++) {
            int cc = fc0 + c2;
            uint32_t so = swz(fr, cc);
            size_t go = kb + cc * 16;
            CP16(sb + S_AHI + so, gAhi + go);
            CP16(sb + S_ALO + so, gAlo + go);
            CP16(sb + S_BHI + so, gBhi + go);
            CP16(sb + S_BLO + so, gBlo + go);
        }
        CP_COMMIT();
    }

    for (int t = 0; t < nT; t++) {
        const int st = (t & 1) * STG;
        if (t + 1 < nT) {
            const int sn = ((t + 1) & 1) * STG;
            const size_t kb = (size_t)(t + 1) * 64;   // 32 bf16 = 64 bytes
            #pragma unroll
            for (int c2 = 0; c2 < 2; c2++) {
                int cc = fc0 + c2;
                uint32_t so = swz(fr, cc);
                size_t go = kb + cc * 16;
                CP16(sb + sn + S_AHI + so, gAhi + go);
                CP16(sb + sn + S_ALO + so, gAlo + go);
                CP16(sb + sn + S_BHI + so, gBhi + go);
                CP16(sb + sn + S_BLO + so, gBlo + go);
            }
            CP_COMMIT();
            CP_WAIT(1);
        } else {
            CP_WAIT(0);
        }
        __syncthreads();

        #pragma unroll
        for (int kk = 0; kk < 2; kk++) {            // kk*16 within BK=32
            uint32_t ah[2][4], al[2][4];
            #pragma unroll
            for (int mt = 0; mt < 2; mt++) {
                int r = arow + mt * 16;
                uint32_t off = swz(r, (kk << 1) + acs);
                LDSM4(ah[mt], sb + st + S_AHI + off);
                LDSM4(al[mt], sb + st + S_ALO + off);
            }
            #pragma unroll
            for (int p = 0; p < 4; p++) {
                int r = brow0 + p * 16;
                uint32_t off = swz(r, (kk << 1) + bcs);
                uint32_t bh[4], bl[4];
                LDSM4(bh, sb + st + S_BHI + off);
                LDSM4(bl, sb + st + S_BLO + off);
                #pragma unroll
                for (int mt = 0; mt < 2; mt++) {
                    MMA16816(c[mt][2 * p],     ah[mt], bh[0], bh[1]);
                    MMA16816(c[mt][2 * p],     al[mt], bh[0], bh[1]);
                    MMA16816(c[mt][2 * p],     ah[mt], bl[0], bl[1]);
                    MMA16816(c[mt][2 * p + 1], ah[mt], bh[2], bh[3]);
                    MMA16816(c[mt][2 * p + 1], al[mt], bh[2], bh[3]);
                    MMA16816(c[mt][2 * p + 1], ah[mt], bl[2], bl[3]);
                }
            }
        }
        __syncthreads();
    }

    // epilogue: c0,c1 -> (m = l/4, n = 2(l%4)); c2,c3 -> m+8
    #pragma unroll
    for (int mt = 0; mt < 2; mt++) {
        int r = row0 + wr * 32 + mt * 16 + (lane >> 2);
        #pragma unroll
        for (int nt = 0; nt < 8; nt++) {
            int cc = col0 + wc * 64 + nt * 8 + 2 * (lane & 3);
            float b0 = g.bias ? g.bias[cc]     : 0.f;
            float b1 = g.bias ? g.bias[cc + 1] : 0.f;
            float v0 = c[mt][nt][0] + b0, v1 = c[mt][nt][1] + b1;
            float v2 = c[mt][nt][2] + b0, v3 = c[mt][nt][3] + b1;
            if (g.doRelu) {
                v0 = fmaxf(v0, 0.f); v1 = fmaxf(v1, 0.f);
                v2 = fmaxf(v2, 0.f); v3 = fmaxf(v3, 0.f);
            }
            *(float2*)&g.C[(size_t)r * g.ldc + cc]       = make_float2(v0, v1);
            *(float2*)&g.C[(size_t)(r + 8) * g.ldc + cc] = make_float2(v2, v3);
        }
    }
}

// ---------------- bf16 split helpers ----------------------------------------
__device__ __forceinline__ void bsplit(float x, __nv_bfloat16& hi, __nv_bfloat16& lo) {
    hi = __float2bfloat16(x);
    lo = __float2bfloat16(x - __bfloat162float(hi));
}
__device__ __forceinline__ uint32_t bpack(__nv_bfloat16 a, __nv_bfloat16 b) {
    __nv_bfloat162 t = __halves2bfloat162(a, b);
    return *reinterpret_cast<uint32_t*>(&t);
}
__device__ __forceinline__ void split4(float4 v, uint2& hi, uint2& lo) {
    __nv_bfloat16 h0, h1, h2, h3, l0, l1, l2, l3;
    bsplit(v.x, h0, l0); bsplit(v.y, h1, l1);
    bsplit(v.z, h2, l2); bsplit(v.w, h3, l3);
    hi.x = bpack(h0, h1); hi.y = bpack(h2, h3);
    lo.x = bpack(l0, l1); lo.y = bpack(l2, l3);
}

// ---------------- weight packing (transpose + split) -------------------------
__global__ void pack_wxw(const float* __restrict__ Wn, const float* __restrict__ Wn2)
{
    int n = blockIdx.x, t = threadIdx.x;       // 256 blocks, 128 thr
    #pragma unroll
    for (int j = 0; j < 4; j++) {
        int k = j * 128 + t;
        float v = (n < 128) ? Wn[k * 128 + n] : Wn2[k * 128 + (n - 128)];
        __nv_bfloat16 hi, lo; bsplit(v, hi, lo);
        d_WtXWhi[n * 512 + k] = hi; d_WtXWlo[n * 512 + k] = lo;
    }
}
__global__ void pack_we(const float* __restrict__ We, const float* __restrict__ We2)
{
    int n = blockIdx.x, k = threadIdx.x;       // 128 blocks, 256 thr
    __nv_bfloat16 hi, lo;
    bsplit(We [k * 128 + n], hi, lo);
    d_WtEghi[n * 256 + k] = hi; d_WtEglo[n * 256 + k] = lo;
    bsplit(We2[k * 128 + n], hi, lo);
    d_WtQhi [n * 256 + k] = hi; d_WtQlo [n * 256 + k] = lo;
}
__global__ void pack_w1(const float* __restrict__ lrW1,  const float* __restrict__ lrb1,
                        const float* __restrict__ scrW1, const float* __restrict__ scrb1,
                        const float* __restrict__ mrW1,  const float* __restrict__ mrb1)
{
    int n = blockIdx.x, t = threadIdx.x;       // 768 blocks, 128 thr
    const float* W; const float* bb; int cn;
    if (n < 256)      { W = lrW1;  bb = lrb1;  cn = n; }
    else if (n < 512) { W = scrW1; bb = scrb1; cn = n - 256; }
    else              { W = mrW1;  bb = mrb1;  cn = n - 512; }
    #pragma unroll
    for (int j = 0; j < 4; j++) {
        int k = j * 128 + t;
        __nv_bfloat16 hi, lo; bsplit(W[k * 256 + cn], hi, lo);
        d_WtW1hi[n * 512 + k] = hi; d_WtW1lo[n * 512 + k] = lo;
    }
    if (t == 0) d_b1cat[n] = bb[cn];
}

// ---------------- glue kernels ----------------------------------------------
__global__ void mask_x_kernel(const float* __restrict__ nf,
                              const int* __restrict__ num_obj)
{
    int blk = blockIdx.x;                // 2048 blocks, 128 thr
    int b = blk >> 7, n = blk & 127, t = threadIdx.x;
    float4 v = make_float4(0.f, 0.f, 0.f, 0.f);
    if (n < num_obj[b]) v = ((const float4*)nf)[(size_t)blk * 128 + t];
    uint2 hi, lo; split4(v, hi, lo);
    ((uint2*)d_Xhi)[(size_t)blk * 128 + t] = hi;
    ((uint2*)d_Xlo)[(size_t)blk * 128 + t] = lo;
}

__global__ void gather_eg_kernel(const float* __restrict__ ef,
                                 const int* __restrict__ ei,
                                 const int* __restrict__ num_edges)
{
    int blk = blockIdx.x;                // 16384 blocks, 64 thr
    int b = blk >> 10, m = blk & 1023, t = threadIdx.x;
    float4 v = make_float4(0.f, 0.f, 0.f, 0.f);
    if (m < num_edges[b]) {
        int s = ei[b * 2048 + m];
        int d = ei[b * 2048 + 1024 + m];
        v = ((const float4*)ef)[(((size_t)b * 128 + s) * 128 + d) * 64 + t];
    }
    uint2 hi, lo; split4(v, hi, lo);
    ((uint2*)d_Eghi)[(size_t)blk * 64 + t] = hi;
    ((uint2*)d_Eglo)[(size_t)blk * 64 + t] = lo;
}

__global__ void adj_h_kernel(const float* __restrict__ adj,
                             const int* __restrict__ num_obj)
{
    int blk = blockIdx.x;                // 2048 blocks, 128 thr
    int b = blk >> 7, i = blk & 127, t = threadIdx.x;
    int no = num_obj[b];
    float* out = &d_h[(size_t)blk * 128];
    if (i >= no) { out[t] = 0.f; return; }
    __shared__ float arow[128];
    arow[t] = adj[(size_t)blk * 128 + t];
    __syncthreads();
    const float* xw = &d_XWp[(size_t)b * 128 * 256];
    float acc = xw[i * 256 + t];
    for (int j = 0; j < no; ++j) {
        float w = arow[j];
        if (w != 0.f) acc = fmaf(w, xw[j * 256 + t], acc);
    }
    out[t] = fmaxf(acc, 0.f);
}

__global__ void line_g_kernel(const float* __restrict__ ladj,
                              const int* __restrict__ num_edges)
{
    int blk = blockIdx.x;                // 16384 blocks, 128 thr
    int b = blk >> 10, i = blk & 1023, t = threadIdx.x;
    int ne = num_edges[b];
    float* out = &d_g[(size_t)blk * 128];
    if (i >= ne) { out[t] = 0.f; return; }

    __shared__ float lrow[1024];
    __shared__ int   jidx[1024];
    __shared__ float jw[1024];
    __shared__ int   cnt;
    if (t == 0) cnt = 0;
    const float* lp = &ladj[(size_t)blk * 1024];
    for (int j = t; j < 1024; j += 128) lrow[j] = lp[j];
    __syncthreads();
    for (int j = t; j < ne; j += 128) {
        float w = lrow[j];
        if (w != 0.f) { int p = atomicAdd(&cnt, 1); jidx[p] = j; jw[p] = w; }
    }
    __syncthreads();
    const float* ew = &d_EgWe[(size_t)b * 1024 * 128];
    float acc = ew[i * 128 + t];
    int c = cnt;
    for (int k = 0; k < c; ++k)
        acc = fmaf(jw[k], ew[jidx[k] * 128 + t], acc);
    out[t] = fmaxf(acc, 0.f);
}

__global__ void zero_agg_kernel()
{
    d_agg[(size_t)blockIdx.x * 128 + threadIdx.x] = 0.f;
}

__global__ void agg_scatter_kernel(const int* __restrict__ ei,
                                   const int* __restrict__ num_edges)
{
    int blk = blockIdx.x;                // 16384 blocks, 128 thr
    int b = blk >> 10, m = blk & 1023, t = threadIdx.x;
    if (m >= num_edges[b]) return;
    int s = ei[b * 2048 + m];
    float v = d_g[(size_t)blk * 128 + t];
    if (v != 0.f)
        atomicAdd(&d_agg[((size_t)b * 128 + s) * 128 + t], v);
}

__global__ void gather_ef_pair_kernel(const float* __restrict__ ef,
                                      const int* __restrict__ pairs)
{
    int blk = blockIdx.x;                // 8192 blocks, 64 thr
    int b = blk / 512, t = threadIdx.x;
    int p0 = pairs[blk * 2], p1 = pairs[blk * 2 + 1];
    float4 v = ((const float4*)ef)[(((size_t)b * 128 + p0) * 128 + p1) * 64 + t];
    uint2 hi, lo; split4(v, hi, lo);
    ((uint2*)d_EFphi)[(size_t)blk * 64 + t] = hi;
    ((uint2*)d_EFplo)[(size_t)blk * 64 + t] = lo;
}

__global__ void ci_kernel(const int* __restrict__ pairs,
                          const int* __restrict__ num_obj)
{
    int blk = blockIdx.x;                // 8192 blocks, 128 thr
    int b = blk / 512, t = threadIdx.x;
    int p0 = pairs[blk * 2], p1 = pairs[blk * 2 + 1];
    int no = num_obj[b];
    const float* hB = &d_h  [(size_t)b * 128 * 128];
    const float* aB = &d_agg[(size_t)b * 128 * 128];
    const float* xB = &d_XWp[(size_t)b * 128 * 256];
    float h0 = hB[p0 * 128 + t] + hB[p1 * 128 + t];
    float a0 = (p0 < no ? aB[p0 * 128 + t] : 0.f) +
               (p1 < no ? aB[p1 * 128 + t] : 0.f);
    float pm = fmaxf(xB[p0 * 256 + 128 + t] + xB[p1 * 256 + 128 + t], 0.f);
    float q  = d_Qp[(size_t)blk * 128 + t];
    size_t base = (size_t)blk * 512;
    __nv_bfloat16 hi, lo;
    bsplit(h0, hi, lo); d_CIhi[base +       t] = hi; d_CIlo[base +       t] = lo;
    bsplit(a0, hi, lo); d_CIhi[base + 128 + t] = hi; d_CIlo[base + 128 + t] = lo;
    bsplit(pm, hi, lo); d_CIhi[base + 256 + t] = hi; d_CIlo[base + 256 + t] = lo;
    bsplit(q,  hi, lo); d_CIhi[base + 384 + t] = hi; d_CIlo[base + 384 + t] = lo;
}

__global__ void head_out_kernel(const float* __restrict__ lrW2, const float* __restrict__ lrb2,
                                const float* __restrict__ crW2, const float* __restrict__ crb2,
                                const float* __restrict__ mrW2, const float* __restrict__ mrb2,
                                float* __restrict__ out)
{
    int blk = blockIdx.x, t = threadIdx.x;  // 8192 blocks, 32 thr
    __shared__ float hid[768];
    const float* hr = &d_HID[(size_t)blk * 768];
    for (int i = t; i < 768; i += 32) hid[i] = hr[i];
    __syncwarp();

    int col, base, outd;
    const float *W2, *b2;
    float* op;
    if (t < 9)       { col = t;      base = 0;   outd = 9;  W2 = lrW2; b2 = lrb2; op = out + (size_t)blk * 9 + col; }
    else if (t < 15) { col = t - 9;  base = 256; outd = 6;  W2 = crW2; b2 = crb2; op = out + 73728 + (size_t)blk * 6 + col; }
    else if (t < 32) { col = t - 15; base = 512; outd = 17; W2 = mrW2; b2 = mrb2; op = out + 122880 + (size_t)blk * 17 + col; }
    else return;

    float acc = b2[col];
    for (int k = 0; k < 256; ++k)
        acc = fmaf(hid[base + k], W2[k * outd + col], acc);
    *op = acc;
}

// ---------------- launch -----------------------------------------------------
extern "C" void kernel_launch(void* const* d_in, const int* in_sizes, int n_in,
                              void* d_out, int out_size)
{
    const float* nf    = (const float*)d_in[0];
    const float* ef    = (const float*)d_in[1];
    const float* adj   = (const float*)d_in[2];
    const float* ladj  = (const float*)d_in[3];
    const int*   ei    = (const int*)  d_in[4];
    const int*   pairs = (const int*)  d_in[5];
    const int*   nobj  = (const int*)  d_in[6];
    const int*   nedg  = (const int*)  d_in[7];
    const float* Wn    = (const float*)d_in[8];
    const float* We    = (const float*)d_in[9];
    const float* Wn2   = (const float*)d_in[10];
    const float* We2   = (const float*)d_in[11];
    const float* scrW1 = (const float*)d_in[12];
    const float* scrb1 = (const float*)d_in[13];
    const float* scrW2 = (const float*)d_in[14];
    const float* scrb2 = (const float*)d_in[15];
    const float* lrW1  = (const float*)d_in[16];
    const float* lrb1  = (const float*)d_in[17];
    const float* lrW2  = (const float*)d_in[18];
    const float* lrb2  = (const float*)d_in[19];
    const float* mrW1  = (const float*)d_in[20];
    const float* mrb1  = (const float*)d_in[21];
    const float* mrW2  = (const float*)d_in[22];
    const float* mrb2  = (const float*)d_in[23];
    float* out = (float*)d_out;

    cudaFuncSetAttribute(gemm_batch, cudaFuncAttributeMaxDynamicSharedMemorySize, GEMM_SMEM);

    __nv_bfloat16 *pXhi, *pXlo, *pEghi, *pEglo, *pEFphi, *pEFplo, *pCIhi, *pCIlo;
    __nv_bfloat16 *pWtXWhi, *pWtXWlo, *pWtEghi, *pWtEglo, *pWtQhi, *pWtQlo, *pWtW1hi, *pWtW1lo;
    float *pXWp, *pEgWe, *pQp, *pHID, *pb1;
    cudaGetSymbolAddress((void**)&pXhi,    d_Xhi);
    cudaGetSymbolAddress((void**)&pXlo,    d_Xlo);
    cudaGetSymbolAddress((void**)&pEghi,   d_Eghi);
    cudaGetSymbolAddress((void**)&pEglo,   d_Eglo);
    cudaGetSymbolAddress((void**)&pEFphi,  d_EFphi);
    cudaGetSymbolAddress((void**)&pEFplo,  d_EFplo);
    cudaGetSymbolAddress((void**)&pCIhi,   d_CIhi);
    cudaGetSymbolAddress((void**)&pCIlo,   d_CIlo);
    cudaGetSymbolAddress((void**)&pWtXWhi, d_WtXWhi);
    cudaGetSymbolAddress((void**)&pWtXWlo, d_WtXWlo);
    cudaGetSymbolAddress((void**)&pWtEghi, d_WtEghi);
    cudaGetSymbolAddress((void**)&pWtEglo, d_WtEglo);
    cudaGetSymbolAddress((void**)&pWtQhi,  d_WtQhi);
    cudaGetSymbolAddress((void**)&pWtQlo,  d_WtQlo);
    cudaGetSymbolAddress((void**)&pWtW1hi, d_WtW1hi);
    cudaGetSymbolAddress((void**)&pWtW1lo, d_WtW1lo);
    cudaGetSymbolAddress((void**)&pXWp,    d_XWp);
    cudaGetSymbolAddress((void**)&pEgWe,   d_EgWe);
    cudaGetSymbolAddress((void**)&pQp,     d_Qp);
    cudaGetSymbolAddress((void**)&pHID,    d_HID);
    cudaGetSymbolAddress((void**)&pb1,     d_b1cat);

    // 0. weight packing
    pack_wxw<<<256, 128>>>(Wn, Wn2);
    pack_we <<<128, 256>>>(We, We2);
    pack_w1 <<<768, 128>>>(lrW1, lrb1, scrW1, scrb1, mrW1, mrb1);
    // 1. input prep (all three GEMM inputs)
    mask_x_kernel<<<2048, 128>>>(nf, nobj);
    gather_eg_kernel<<<16384, 64>>>(ef, ei, nedg);
    gather_ef_pair_kernel<<<8192, 64>>>(ef, pairs);
    // 2. batched GEMM: XWp (32 blk) | EgWe (128 blk) | Qp (64 blk)
    {
        Gp gp;
        gp.n = 3;
        gp.d[0] = { pXhi,   pXlo,   pWtXWhi, pWtXWlo, pXWp,  nullptr, 256, 512, 2,  32, 0, 0 };
        gp.d[1] = { pEghi,  pEglo,  pWtEghi, pWtEglo, pEgWe, nullptr, 128, 256, 1, 160, 0, 0 };
        gp.d[2] = { pEFphi, pEFplo, pWtQhi,  pWtQlo,  pQp,   nullptr, 128, 256, 1, 224, 1, 0 };
        gemm_batch<<<224, 256, GEMM_SMEM>>>(gp);
    }
    // 3. graph ops
    adj_h_kernel<<<2048, 128>>>(adj, nobj);
    line_g_kernel<<<16384, 128>>>(ladj, nedg);
    zero_agg_kernel<<<2048, 128>>>();
    agg_scatter_kernel<<<16384, 128>>>(ei, nedg);
    // 4. CI assembly
    ci_kernel<<<8192, 128>>>(pairs, nobj);
    // 5. HID = relu(CI @ W1cat + b1cat)   (384 blocks)
    {
        Gp gp;
        gp.n = 1;
        gp.d[0] = { pCIhi, pCIlo, pWtW1hi, pWtW1lo, pHID, pb1, 768, 512, 6, 384, 1, 0 };
        gp.d[1] = gp.d[0];
        gp.d[2] = gp.d[0];
        gemm_batch<<<384, 256, GEMM_SMEM>>>(gp);
    }
    // 6. heads -> out
    head_out_kernel<<<8192, 32>>>(lrW2, lrb2, scrW2, scrb2, mrW2, mrb2, out);
}

// round 7
// speedup vs baseline: 2.6561x; 1.2367x over previous
#include <cuda_runtime.h>
#include <cuda_bf16.h>
#include <cstdint>
#include <cstddef>

// Problem dims
#define BB   16
#define NN   128
#define MMx  1024
#define DNx  512
#define DEx  256
#define PPx  512

// ---------------- scratch (static __device__, no allocation) ----------------
__device__ __nv_bfloat16 d_Xhi [BB*NN*DNx],  d_Xlo [BB*NN*DNx];   // 2048x512
__device__ float         d_XWp [BB*NN*256];                        // [XW|Xp]
__device__ float         d_h   [BB*NN*128];
__device__ __nv_bfloat16 d_Eghi[BB*MMx*DEx], d_Eglo[BB*MMx*DEx];  // 16384x256
__device__ float         d_EgWe[BB*MMx*128];
__device__ float         d_g   [BB*MMx*128];
__device__ float         d_agg [BB*NN*128];
__device__ __nv_bfloat16 d_EFphi[BB*PPx*DEx], d_EFplo[BB*PPx*DEx];// 8192x256
__device__ float         d_Qp  [BB*PPx*128];
__device__ __nv_bfloat16 d_CIhi[BB*PPx*512], d_CIlo[BB*PPx*512];  // 8192x512
// transposed + split weights: [N][K] K-major
__device__ __nv_bfloat16 d_WtXWhi[256*512], d_WtXWlo[256*512];
__device__ __nv_bfloat16 d_WtEghi[128*256], d_WtEglo[128*256];
__device__ __nv_bfloat16 d_WtQhi [128*256], d_WtQlo [128*256];
__device__ __nv_bfloat16 d_WtW1hi[768*512], d_WtW1lo[768*512];
__device__ float         d_b1cat[768];
__device__ float         d_W2cat[768*32];   // padded [hidden][32] fp32

// ---------------- asm helpers ------------------------------------------------
__device__ __forceinline__ uint32_t smem_u32(const void* p) {
    uint32_t a;
    asm("{ .reg .u64 t; cvta.to.shared.u64 t, %1; cvt.u32.u64 %0, t; }" : "=r"(a) : "l"(p));
    return a;
}
#define CP16(sa, ga) \
    asm volatile("cp.async.cg.shared.global [%0], [%1], 16;" :: "r"(sa), "l"(ga))
#define CP_COMMIT() asm volatile("cp.async.commit_group;" ::: "memory")
#define CP_WAIT(n)  asm volatile("cp.async.wait_group %0;" :: "n"(n) : "memory")

#define LDSM4(r, a) \
    asm volatile("ldmatrix.sync.aligned.m8n8.x4.shared.b16 {%0,%1,%2,%3}, [%4];" \
        : "=r"((r)[0]), "=r"((r)[1]), "=r"((r)[2]), "=r"((r)[3]) : "r"(a))

#define MMA16816(c, a, b0, b1) \
    asm volatile("mma.sync.aligned.m16n8k16.row.col.f32.bf16.bf16.f32 " \
        "{%0,%1,%2,%3},{%4,%5,%6,%7},{%8,%9},{%0,%1,%2,%3};" \
        : "+f"((c)[0]), "+f"((c)[1]), "+f"((c)[2]), "+f"((c)[3]) \
        : "r"((a)[0]), "r"((a)[1]), "r"((a)[2]), "r"((a)[3]), "r"(b0), "r"(b1))

// ---------------- batched bf16 tensor-core GEMM ------------------------------
// C[M,N] = op(A @ B^T (+bias) (relu)); 3-term compensated bf16.
// fuse=1: instead of writing C, multiply relu(H) by W2cat slice and
// atomicAdd head outputs into outp (out pre-initialized with biases).
struct Gd {
    const __nv_bfloat16 *Ahi, *Alo, *Bhi, *Blo;
    float* C; const float* bias;
    const float* W2; float* outp;
    int ldc, K, tilesX, blkEnd, doRelu, fuse;
};
struct Gp { Gd d[3]; int n; };

#define S_AHI 0
#define S_ALO 8192
#define S_BHI 16384
#define S_BLO 24576
#define STG   32768
#define GEMM_SMEM_MAIN  (2 * STG)          // 64 KB
#define HS_STRIDE 130
#define GEMM_SMEM_FUSE  (128 * HS_STRIDE * 4)   // 66560
#define GEMM_SMEM_MAX   GEMM_SMEM_FUSE

// swizzled byte offset of 16B chunk c (0..3) in row r (row = 64B)
__device__ __forceinline__ uint32_t swz(int r, int c) {
    return (uint32_t)(r * 64 + ((c ^ ((r >> 1) & 3)) << 4));
}

__global__ __launch_bounds__(256, 2) void gemm_batch(Gp gp)
{
    extern __shared__ char smem[];
    const uint32_t sb = smem_u32(smem);

    int bid = blockIdx.x, di = 0;
    while (di < gp.n - 1 && bid >= gp.d[di].blkEnd) di++;
    const Gd g = gp.d[di];
    const int base  = di ? gp.d[di - 1].blkEnd : 0;
    const int local = bid - base;
    const int row0  = (local / g.tilesX) * 128;
    const int col0  = (local % g.tilesX) * 128;
    const int K     = g.K;
    const int nT    = K >> 5;

    const int tid = threadIdx.x, lane = tid & 31, wid = tid >> 5;
    const int wr = wid & 3, wc = wid >> 2;

    const int fr = tid >> 1, fc0 = (tid & 1) * 2;
    const char* gAhi = (const char*)g.Ahi + ((size_t)(row0 + fr) * K) * 2;
    const char* gAlo = (const char*)g.Alo + ((size_t)(row0 + fr) * K) * 2;
    const char* gBhi = (const char*)g.Bhi + ((size_t)(col0 + fr) * K) * 2;
    const char* gBlo = (const char*)g.Blo + ((size_t)(col0 + fr) * K) * 2;

    float c[2][8][4];
    #pragma unroll
    for (int mt = 0; mt < 2; mt++)
        #pragma unroll
        for (int nt = 0; nt < 8; nt++)
            #pragma unroll
            for (int i = 0; i < 4; i++) c[mt][nt][i] = 0.f;

    const int arow = wr * 32 + (lane & 7) + (lane & 8);
    const int acs  = (lane & 16) ? 1 : 0;
    const int brow0 = wc * 64 + (lane & 7) + ((lane & 16) ? 8 : 0);
    const int bcs   = (lane & 8) ? 1 : 0;

    {   // prologue: tile 0 -> stage 0
        #pragma unroll
        for (int c2 = 0; c2 < 2; c2++) {
            int cc = fc0 + c2;
            uint32_t so = swz(fr, cc);
            size_t go = cc * 16;
            CP16(sb + S_AHI + so, gAhi + go);
            CP16(sb + S_ALO + so, gAlo + go);
            CP16(sb + S_BHI + so, gBhi + go);
            CP16(sb + S_BLO + so, gBlo + go);
        }
        CP_COMMIT();
    }

    for (int t = 0; t < nT; t++) {
        const int st = (t & 1) * STG;
        if (t + 1 < nT) {
            const int sn = ((t + 1) & 1) * STG;
            const size_t kb = (size_t)(t + 1) * 64;
            #pragma unroll
            for (int c2 = 0; c2 < 2; c2++) {
                int cc = fc0 + c2;
                uint32_t so = swz(fr, cc);
                size_t go = kb + cc * 16;
                CP16(sb + sn + S_AHI + so, gAhi + go);
                CP16(sb + sn + S_ALO + so, gAlo + go);
                CP16(sb + sn + S_BHI + so, gBhi + go);
                CP16(sb + sn + S_BLO + so, gBlo + go);
            }
            CP_COMMIT();
            CP_WAIT(1);
        } else {
            CP_WAIT(0);
        }
        __syncthreads();

        #pragma unroll
        for (int kk = 0; kk < 2; kk++) {
            uint32_t ah[2][4], al[2][4];
            #pragma unroll
            for (int mt = 0; mt < 2; mt++) {
                int r = arow + mt * 16;
                uint32_t off = swz(r, (kk << 1) + acs);
                LDSM4(ah[mt], sb + st + S_AHI + off);
                LDSM4(al[mt], sb + st + S_ALO + off);
            }
            #pragma unroll
            for (int p = 0; p < 4; p++) {
                int r = brow0 + p * 16;
                uint32_t off = swz(r, (kk << 1) + bcs);
                uint32_t bh[4], bl[4];
                LDSM4(bh, sb + st + S_BHI + off);
                LDSM4(bl, sb + st + S_BLO + off);
                #pragma unroll
                for (int mt = 0; mt < 2; mt++) {
                    MMA16816(c[mt][2 * p],     ah[mt], bh[0], bh[1]);
                    MMA16816(c[mt][2 * p],     al[mt], bh[0], bh[1]);
                    MMA16816(c[mt][2 * p],     ah[mt], bl[0], bl[1]);
                    MMA16816(c[mt][2 * p + 1], ah[mt], bh[2], bh[3]);
                    MMA16816(c[mt][2 * p + 1], al[mt], bh[2], bh[3]);
                    MMA16816(c[mt][2 * p + 1], ah[mt], bl[2], bl[3]);
                }
            }
        }
        __syncthreads();
    }

    if (!g.fuse) {
        #pragma unroll
        for (int mt = 0; mt < 2; mt++) {
            int r = row0 + wr * 32 + mt * 16 + (lane >> 2);
            #pragma unroll
            for (int nt = 0; nt < 8; nt++) {
                int cc = col0 + wc * 64 + nt * 8 + 2 * (lane & 3);
                float b0 = g.bias ? g.bias[cc]     : 0.f;
                float b1 = g.bias ? g.bias[cc + 1] : 0.f;
                float v0 = c[mt][nt][0] + b0, v1 = c[mt][nt][1] + b1;
                float v2 = c[mt][nt][2] + b0, v3 = c[mt][nt][3] + b1;
                if (g.doRelu) {
                    v0 = fmaxf(v0, 0.f); v1 = fmaxf(v1, 0.f);
                    v2 = fmaxf(v2, 0.f); v3 = fmaxf(v3, 0.f);
                }
                *(float2*)&g.C[(size_t)r * g.ldc + cc]       = make_float2(v0, v1);
                *(float2*)&g.C[(size_t)(r + 8) * g.ldc + cc] = make_float2(v2, v3);
            }
        }
        return;
    }

    // ---- fused head epilogue: H = relu(c + bias) -> smem; P = H @ W2slice ---
    float* Hs = (float*)smem;               // [128][HS_STRIDE]
    #pragma unroll
    for (int mt = 0; mt < 2; mt++) {
        int rl = wr * 32 + mt * 16 + (lane >> 2);
        #pragma unroll
        for (int nt = 0; nt < 8; nt++) {
            int cl = wc * 64 + nt * 8 + 2 * (lane & 3);
            float b0 = g.bias[col0 + cl], b1 = g.bias[col0 + cl + 1];
            float v0 = fmaxf(c[mt][nt][0] + b0, 0.f);
            float v1 = fmaxf(c[mt][nt][1] + b1, 0.f);
            float v2 = fmaxf(c[mt][nt][2] + b0, 0.f);
            float v3 = fmaxf(c[mt][nt][3] + b1, 0.f);
            *(float2*)&Hs[rl * HS_STRIDE + cl]       = make_float2(v0, v1);
            *(float2*)&Hs[(rl + 8) * HS_STRIDE + cl] = make_float2(v2, v3);
        }
    }
    __syncthreads();

    const int head = col0 >> 8;                         // 0:lr 1:cr 2:mr
    const int outd = (head == 0) ? 9 : (head == 1) ? 6 : 17;
    const size_t obase = (head == 0) ? 0 : (head == 1) ? 73728 : 122880;
    const float* W2p = g.W2 + (size_t)col0 * 32;        // rows col0..col0+127

    const int rg = tid >> 3;        // 0..31 -> rows 4rg..
    const int cg = tid & 7;         // 0..7  -> cols 4cg..
    float acc[4][4];
    #pragma unroll
    for (int i = 0; i < 4; i++)
        #pragma unroll
        for (int j = 0; j < 4; j++) acc[i][j] = 0.f;

    #pragma unroll 4
    for (int k = 0; k < 128; k++) {
        float4 w = __ldg((const float4*)(W2p + (size_t)k * 32 + cg * 4));
        #pragma unroll
        for (int i = 0; i < 4; i++) {
            float hv = Hs[(rg * 4 + i) * HS_STRIDE + k];
            acc[i][0] = fmaf(hv, w.x, acc[i][0]);
            acc[i][1] = fmaf(hv, w.y, acc[i][1]);
            acc[i][2] = fmaf(hv, w.z, acc[i][2]);
            acc[i][3] = fmaf(hv, w.w, acc[i][3]);
        }
    }
    #pragma unroll
    for (int i = 0; i < 4; i++) {
        int row = row0 + rg * 4 + i;
        #pragma unroll
        for (int j = 0; j < 4; j++) {
            int cc = cg * 4 + j;
            if (cc < outd)
                atomicAdd(&g.outp[obase + (size_t)row * outd + cc], acc[i][j]);
        }
    }
}

// ---------------- bf16 split helpers ----------------------------------------
__device__ __forceinline__ void bsplit(float x, __nv_bfloat16& hi, __nv_bfloat16& lo) {
    hi = __float2bfloat16(x);
    lo = __float2bfloat16(x - __bfloat162float(hi));
}
__device__ __forceinline__ uint32_t bpack(__nv_bfloat16 a, __nv_bfloat16 b) {
    __nv_bfloat162 t = __halves2bfloat162(a, b);
    return *reinterpret_cast<uint32_t*>(&t);
}
__device__ __forceinline__ void split4(float4 v, uint2& hi, uint2& lo) {
    __nv_bfloat16 h0, h1, h2, h3, l0, l1, l2, l3;
    bsplit(v.x, h0, l0); bsplit(v.y, h1, l1);
    bsplit(v.z, h2, l2); bsplit(v.w, h3, l3);
    hi.x = bpack(h0, h1); hi.y = bpack(h2, h3);
    lo.x = bpack(l0, l1); lo.y = bpack(l2, l3);
}

// ---------------- pack_all: all weight packing in one launch -----------------
// grid: [0,256) wxw | [256,384) we | [384,1152) w1 + W2cat + b1cat.  256 thr.
__global__ void pack_all(const float* __restrict__ Wn,  const float* __restrict__ Wn2,
                         const float* __restrict__ We,  const float* __restrict__ We2,
                         const float* __restrict__ lrW1,  const float* __restrict__ lrb1,
                         const float* __restrict__ scrW1, const float* __restrict__ scrb1,
                         const float* __restrict__ mrW1,  const float* __restrict__ mrb1,
                         const float* __restrict__ lrW2,  const float* __restrict__ crW2,
                         const float* __restrict__ mrW2)
{
    int blk = blockIdx.x, t = threadIdx.x;
    if (blk < 256) {
        int n = blk;
        #pragma unroll
        for (int j = 0; j < 2; j++) {
            int k = t + j * 256;
            float v = (n < 128) ? Wn[k * 128 + n] : Wn2[k * 128 + (n - 128)];
            __nv_bfloat16 hi, lo; bsplit(v, hi, lo);
            d_WtXWhi[n * 512 + k] = hi; d_WtXWlo[n * 512 + k] = lo;
        }
    } else if (blk < 384) {
        int n = blk - 256, k = t;
        __nv_bfloat16 hi, lo;
        bsplit(We [k * 128 + n], hi, lo);
        d_WtEghi[n * 256 + k] = hi; d_WtEglo[n * 256 + k] = lo;
        bsplit(We2[k * 128 + n], hi, lo);
        d_WtQhi [n * 256 + k] = hi; d_WtQlo [n * 256 + k] = lo;
    } else {
        int n = blk - 384;                 // 0..767
        const float* W; const float* bb; const float* W2; int cn, outd;
        if (n < 256)      { W = lrW1;  bb = lrb1;  W2 = lrW2; cn = n;       outd = 9;  }
        else if (n < 512) { W = scrW1; bb = scrb1; W2 = crW2; cn = n - 256; outd = 6;  }
        else              { W = mrW1;  bb = mrb1;  W2 = mrW2; cn = n - 512; outd = 17; }
        #pragma unroll
        for (int j = 0; j < 2; j++) {
            int k = t + j * 256;
            __nv_bfloat16 hi, lo; bsplit(W[k * 256 + cn], hi, lo);
            d_WtW1hi[n * 512 + k] = hi; d_WtW1lo[n * 512 + k] = lo;
        }
        if (t == 0) d_b1cat[n] = bb[cn];
        if (t < 32) d_W2cat[n * 32 + t] = (t < outd) ? W2[cn * outd + t] : 0.f;
    }
}

// ---------------- prep_all: gathers + masks + agg-zero + out bias init -------
// grid: [0,2048) maskX+aggzero | [2048,10240) gatherEg | [10240,14336) gatherEFp
//       | [14336,14848) out init.  128 thr.
__global__ void prep_all(const float* __restrict__ nf, const float* __restrict__ ef,
                         const int* __restrict__ ei, const int* __restrict__ pairs,
                         const int* __restrict__ num_obj, const int* __restrict__ num_edges,
                         const float* __restrict__ lrb2, const float* __restrict__ crb2,
                         const float* __restrict__ mrb2, float* __restrict__ out)
{
    int blk = blockIdx.x, t = threadIdx.x;
    if (blk < 2048) {
        int b = blk >> 7, n = blk & 127;
        float4 v = make_float4(0.f, 0.f, 0.f, 0.f);
        if (n < num_obj[b]) v = ((const float4*)nf)[(size_t)blk * 128 + t];
        uint2 hi, lo; split4(v, hi, lo);
        ((uint2*)d_Xhi)[(size_t)blk * 128 + t] = hi;
        ((uint2*)d_Xlo)[(size_t)blk * 128 + t] = lo;
        d_agg[(size_t)blk * 128 + t] = 0.f;
    } else if (blk < 10240) {
        int idx = (blk - 2048) * 2 + (t >> 6);     // 0..16383
        int b = idx >> 10, m = idx & 1023, tt = t & 63;
        float4 v = make_float4(0.f, 0.f, 0.f, 0.f);
        if (m < num_edges[b]) {
            int s = ei[b * 2048 + m];
            int d = ei[b * 2048 + 1024 + m];
            v = ((const float4*)ef)[(((size_t)b * 128 + s) * 128 + d) * 64 + tt];
        }
        uint2 hi, lo; split4(v, hi, lo);
        ((uint2*)d_Eghi)[(size_t)idx * 64 + tt] = hi;
        ((uint2*)d_Eglo)[(size_t)idx * 64 + tt] = lo;
    } else if (blk < 14336) {
        int idx = (blk - 10240) * 2 + (t >> 6);    // 0..8191
        int b = idx / 512, tt = t & 63;
        int p0 = pairs[idx * 2], p1 = pairs[idx * 2 + 1];
        float4 v = ((const float4*)ef)[(((size_t)b * 128 + p0) * 128 + p1) * 64 + tt];
        uint2 hi, lo; split4(v, hi, lo);
        ((uint2*)d_EFphi)[(size_t)idx * 64 + tt] = hi;
        ((uint2*)d_EFplo)[(size_t)idx * 64 + tt] = lo;
    } else {
        int base = (blk - 14336) * 512 + t * 4;    // 4 floats each, 262144 total
        #pragma unroll
        for (int j = 0; j < 4; j++) {
            int i = base + j;
            float v;
            if (i < 73728)       v = lrb2[i % 9];
            else if (i < 122880) v = crb2[(i - 73728) % 6];
            else                 v = mrb2[(i - 122880) % 17];
            out[i] = v;
        }
    }
}

// ---------------- graph_all: adj_h + line_g ----------------------------------
// grid: [0,2048) adj_h | [2048,18432) line_g.  128 thr.
__global__ void graph_all(const float* __restrict__ adj, const float* __restrict__ ladj,
                          const int* __restrict__ num_obj, const int* __restrict__ num_edges)
{
    __shared__ float s_lrow[1024];
    __shared__ int   s_jidx[1024];
    __shared__ float s_jw[1024];
    __shared__ int   s_cnt;

    int blk = blockIdx.x, t = threadIdx.x;
    if (blk < 2048) {
        int b = blk >> 7, i = blk & 127;
        int no = num_obj[b];
        float* outp = &d_h[(size_t)blk * 128];
        if (i >= no) { outp[t] = 0.f; return; }
        s_lrow[t] = adj[(size_t)blk * 128 + t];
        __syncthreads();
        const float* xw = &d_XWp[(size_t)b * 128 * 256];
        float acc = xw[i * 256 + t];
        for (int j = 0; j < no; ++j) {
            float w = s_lrow[j];
            if (w != 0.f) acc = fmaf(w, xw[j * 256 + t], acc);
        }
        outp[t] = fmaxf(acc, 0.f);
    } else {
        int lb = blk - 2048;
        int b = lb >> 10, i = lb & 1023;
        int ne = num_edges[b];
        float* outp = &d_g[(size_t)lb * 128];
        if (i >= ne) { outp[t] = 0.f; return; }
        if (t == 0) s_cnt = 0;
        const float* lp = &ladj[(size_t)lb * 1024];
        for (int j = t; j < 1024; j += 128) s_lrow[j] = lp[j];
        __syncthreads();
        for (int j = t; j < ne; j += 128) {
            float w = s_lrow[j];
            if (w != 0.f) { int p = atomicAdd(&s_cnt, 1); s_jidx[p] = j; s_jw[p] = w; }
        }
        __syncthreads();
        const float* ew = &d_EgWe[(size_t)b * 1024 * 128];
        float acc = ew[i * 128 + t];
        int c = s_cnt;
        for (int k = 0; k < c; ++k)
            acc = fmaf(s_jw[k], ew[s_jidx[k] * 128 + t], acc);
        outp[t] = fmaxf(acc, 0.f);
    }
}

__global__ void agg_scatter_kernel(const int* __restrict__ ei,
                                   const int* __restrict__ num_edges)
{
    int blk = blockIdx.x;                // 16384 blocks, 128 thr
    int b = blk >> 10, m = blk & 1023, t = threadIdx.x;
    if (m >= num_edges[b]) return;
    int s = ei[b * 2048 + m];
    float v = d_g[(size_t)blk * 128 + t];
    if (v != 0.f)
        atomicAdd(&d_agg[((size_t)b * 128 + s) * 128 + t], v);
}

__global__ void ci_kernel(const int* __restrict__ pairs,
                          const int* __restrict__ num_obj)
{
    int blk = blockIdx.x;                // 8192 blocks, 128 thr
    int b = blk / 512, t = threadIdx.x;
    int p0 = pairs[blk * 2], p1 = pairs[blk * 2 + 1];
    int no = num_obj[b];
    const float* hB = &d_h  [(size_t)b * 128 * 128];
    const float* aB = &d_agg[(size_t)b * 128 * 128];
    const float* xB = &d_XWp[(size_t)b * 128 * 256];
    float h0 = hB[p0 * 128 + t] + hB[p1 * 128 + t];
    float a0 = (p0 < no ? aB[p0 * 128 + t] : 0.f) +
               (p1 < no ? aB[p1 * 128 + t] : 0.f);
    float pm = fmaxf(xB[p0 * 256 + 128 + t] + xB[p1 * 256 + 128 + t], 0.f);
    float q  = d_Qp[(size_t)blk * 128 + t];
    size_t base = (size_t)blk * 512;
    __nv_bfloat16 hi, lo;
    bsplit(h0, hi, lo); d_CIhi[base +       t] = hi; d_CIlo[base +       t] = lo;
    bsplit(a0, hi, lo); d_CIhi[base + 128 + t] = hi; d_CIlo[base + 128 + t] = lo;
    bsplit(pm, hi, lo); d_CIhi[base + 256 + t] = hi; d_CIlo[base + 256 + t] = lo;
    bsplit(q,  hi, lo); d_CIhi[base + 384 + t] = hi; d_CIlo[base + 384 + t] = lo;
}

// ---------------- launch -----------------------------------------------------
extern "C" void kernel_launch(void* const* d_in, const int* in_sizes, int n_in,
                              void* d_out, int out_size)
{
    const float* nf    = (const float*)d_in[0];
    const float* ef    = (const float*)d_in[1];
    const float* adj   = (const float*)d_in[2];
    const float* ladj  = (const float*)d_in[3];
    const int*   ei    = (const int*)  d_in[4];
    const int*   pairs = (const int*)  d_in[5];
    const int*   nobj  = (const int*)  d_in[6];
    const int*   nedg  = (const int*)  d_in[7];
    const float* Wn    = (const float*)d_in[8];
    const float* We    = (const float*)d_in[9];
    const float* Wn2   = (const float*)d_in[10];
    const float* We2   = (const float*)d_in[11];
    const float* scrW1 = (const float*)d_in[12];
    const float* scrb1 = (const float*)d_in[13];
    const float* scrW2 = (const float*)d_in[14];
    const float* scrb2 = (const float*)d_in[15];
    const float* lrW1  = (const float*)d_in[16];
    const float* lrb1  = (const float*)d_in[17];
    const float* lrW2  = (const float*)d_in[18];
    const float* lrb2  = (const float*)d_in[19];
    const float* mrW1  = (const float*)d_in[20];
    const float* mrb1  = (const float*)d_in[21];
    const float* mrW2  = (const float*)d_in[22];
    const float* mrb2  = (const float*)d_in[23];
    float* out = (float*)d_out;

    cudaFuncSetAttribute(gemm_batch, cudaFuncAttributeMaxDynamicSharedMemorySize, GEMM_SMEM_MAX);

    __nv_bfloat16 *pXhi, *pXlo, *pEghi, *pEglo, *pEFphi, *pEFplo, *pCIhi, *pCIlo;
    __nv_bfloat16 *pWtXWhi, *pWtXWlo, *pWtEghi, *pWtEglo, *pWtQhi, *pWtQlo, *pWtW1hi, *pWtW1lo;
    float *pXWp, *pEgWe, *pQp, *pb1, *pW2;
    cudaGetSymbolAddress((void**)&pXhi,    d_Xhi);
    cudaGetSymbolAddress((void**)&pXlo,    d_Xlo);
    cudaGetSymbolAddress((void**)&pEghi,   d_Eghi);
    cudaGetSymbolAddress((void**)&pEglo,   d_Eglo);
    cudaGetSymbolAddress((void**)&pEFphi,  d_EFphi);
    cudaGetSymbolAddress((void**)&pEFplo,  d_EFplo);
    cudaGetSymbolAddress((void**)&pCIhi,   d_CIhi);
    cudaGetSymbolAddress((void**)&pCIlo,   d_CIlo);
    cudaGetSymbolAddress((void**)&pWtXWhi, d_WtXWhi);
    cudaGetSymbolAddress((void**)&pWtXWlo, d_WtXWlo);
    cudaGetSymbolAddress((void**)&pWtEghi, d_WtEghi);
    cudaGetSymbolAddress((void**)&pWtEglo, d_WtEglo);
    cudaGetSymbolAddress((void**)&pWtQhi,  d_WtQhi);
    cudaGetSymbolAddress((void**)&pWtQlo,  d_WtQlo);
    cudaGetSymbolAddress((void**)&pWtW1hi, d_WtW1hi);
    cudaGetSymbolAddress((void**)&pWtW1lo, d_WtW1lo);
    cudaGetSymbolAddress((void**)&pXWp,    d_XWp);
    cudaGetSymbolAddress((void**)&pEgWe,   d_EgWe);
    cudaGetSymbolAddress((void**)&pQp,     d_Qp);
    cudaGetSymbolAddress((void**)&pb1,     d_b1cat);
    cudaGetSymbolAddress((void**)&pW2,     d_W2cat);

    // 1. all packing in one node
    pack_all<<<1152, 256>>>(Wn, Wn2, We, We2, lrW1, lrb1, scrW1, scrb1,
                            mrW1, mrb1, lrW2, scrW2, mrW2);
    // 2. all input prep + agg zero + out bias init
    prep_all<<<14848, 128>>>(nf, ef, ei, pairs, nobj, nedg, lrb2, scrb2, mrb2, out);
    // 3. batched GEMM: XWp (32) | EgWe (128) | Qp (64)
    {
        Gp gp;
        gp.n = 3;
        gp.d[0] = { pXhi,   pXlo,   pWtXWhi, pWtXWlo, pXWp,  nullptr, nullptr, nullptr, 256, 512, 2,  32, 0, 0 };
        gp.d[1] = { pEghi,  pEglo,  pWtEghi, pWtEglo, pEgWe, nullptr, nullptr, nullptr, 128, 256, 1, 160, 0, 0 };
        gp.d[2] = { pEFphi, pEFplo, pWtQhi,  pWtQlo,  pQp,   nullptr, nullptr, nullptr, 128, 256, 1, 224, 1, 0 };
        gemm_batch<<<224, 256, GEMM_SMEM_MAIN>>>(gp);
    }
    // 4. adj conv + line conv
    graph_all<<<18432, 128>>>(adj, ladj, nobj, nedg);
    // 5. scatter-add by src
    agg_scatter_kernel<<<16384, 128>>>(ei, nedg);
    // 6. classifier input assembly
    ci_kernel<<<8192, 128>>>(pairs, nobj);
    // 7. fused W1 GEMM + relu + heads -> out (atomic partials)
    {
        Gp gp;
        gp.n = 1;
        gp.d[0] = { pCIhi, pCIlo, pWtW1hi, pWtW1lo, nullptr, pb1, pW2, out, 768, 512, 6, 384, 1, 1 };
        gp.d[1] = gp.d[0];
        gp.d[2] = gp.d[0];
        gemm_batch<<<384, 256, GEMM_SMEM_FUSE>>>(gp);
    }
}

// round 8
// speedup vs baseline: 3.7292x; 1.4040x over previous
#include <cuda_runtime.h>
#include <cuda_fp16.h>
#include <cstdint>
#include <cstddef>

// Problem dims
#define BB   16
#define NN   128
#define MMx  1024
#define DNx  512
#define DEx  256
#define PPx  512

// ---------------- scratch (static __device__, no allocation) ----------------
__device__ __half d_Xh  [BB*NN*DNx];      // masked node feats fp16 (2048x512)
__device__ float  d_XWp [BB*NN*256];      // [XW|Xp]
__device__ float  d_h   [BB*NN*128];
__device__ __half d_Egh [BB*MMx*DEx];     // gathered edge feats    (16384x256)
__device__ float  d_EgWe[BB*MMx*128];
__device__ float  d_agg [BB*NN*128];
__device__ __half d_EFph[BB*PPx*DEx];     // edge feats at pairs    (8192x256)
__device__ float  d_Qp  [BB*PPx*128];
__device__ __half d_CIh [BB*PPx*512];     // classifier input       (8192x512)
// transposed + split weights: [N][K] K-major, fp16 hi/lo
__device__ __half d_WtXWhi[256*512], d_WtXWlo[256*512];
__device__ __half d_WtEghi[128*256], d_WtEglo[128*256];
__device__ __half d_WtQhi [128*256], d_WtQlo [128*256];
__device__ __half d_WtW1hi[768*512], d_WtW1lo[768*512];
__device__ float  d_b1cat[768];
__device__ float  d_W2cat[768*32];        // padded [hidden][32] fp32

// ---------------- asm helpers ------------------------------------------------
__device__ __forceinline__ uint32_t smem_u32(const void* p) {
    uint32_t a;
    asm("{ .reg .u64 t; cvta.to.shared.u64 t, %1; cvt.u32.u64 %0, t; }" : "=r"(a) : "l"(p));
    return a;
}
#define CP16(sa, ga) \
    asm volatile("cp.async.cg.shared.global [%0], [%1], 16;" :: "r"(sa), "l"(ga))
#define CP_COMMIT() asm volatile("cp.async.commit_group;" ::: "memory")
#define CP_WAIT(n)  asm volatile("cp.async.wait_group %0;" :: "n"(n) : "memory")

#define LDSM4(r, a) \
    asm volatile("ldmatrix.sync.aligned.m8n8.x4.shared.b16 {%0,%1,%2,%3}, [%4];" \
        : "=r"((r)[0]), "=r"((r)[1]), "=r"((r)[2]), "=r"((r)[3]) : "r"(a))

#define MMAH(c, a, b0, b1) \
    asm volatile("mma.sync.aligned.m16n8k16.row.col.f32.f16.f16.f32 " \
        "{%0,%1,%2,%3},{%4,%5,%6,%7},{%8,%9},{%0,%1,%2,%3};" \
        : "+f"((c)[0]), "+f"((c)[1]), "+f"((c)[2]), "+f"((c)[3]) \
        : "r"((a)[0]), "r"((a)[1]), "r"((a)[2]), "r"((a)[3]), "r"(b0), "r"(b1))

// ---------------- batched fp16 tensor-core GEMM ------------------------------
// C[M,N] = op(A @ B^T (+bias) (relu)); A fp16, B = Bhi+Blo fp16 (2-term).
// fuse=1: heads epilogue (relu(H) @ W2cat slice, atomicAdd into out).
struct Gd {
    const __half *A, *Bhi, *Blo;
    float* C; const float* bias;
    const float* W2; float* outp;
    int ldc, K, tilesX, blkEnd, doRelu, fuse;
};
struct Gp { Gd d[3]; int n; };

#define S_AHI 0
#define S_BHI 8192
#define S_BLO 16384
#define STG   24576
#define GEMM_SMEM_MAIN  (2 * STG)               // 48 KB
#define HS_STRIDE 130
#define GEMM_SMEM_FUSE  (128 * HS_STRIDE * 4)   // 66560
#define GEMM_SMEM_MAX   GEMM_SMEM_FUSE

// swizzled byte offset of 16B chunk c (0..3) in row r (row = 64B)
__device__ __forceinline__ uint32_t swz(int r, int c) {
    return (uint32_t)(r * 64 + ((c ^ ((r >> 1) & 3)) << 4));
}

__global__ __launch_bounds__(256, 2) void gemm_batch(Gp gp)
{
    extern __shared__ char smem[];
    const uint32_t sb = smem_u32(smem);

    int bid = blockIdx.x, di = 0;
    while (di < gp.n - 1 && bid >= gp.d[di].blkEnd) di++;
    const Gd g = gp.d[di];
    const int base  = di ? gp.d[di - 1].blkEnd : 0;
    const int local = bid - base;
    const int row0  = (local / g.tilesX) * 128;
    const int col0  = (local % g.tilesX) * 128;
    const int K     = g.K;
    const int nT    = K >> 5;

    const int tid = threadIdx.x, lane = tid & 31, wid = tid >> 5;
    const int wr = wid & 3, wc = wid >> 2;

    const int fr = tid >> 1, fc0 = (tid & 1) * 2;
    const char* gA  = (const char*)g.A   + ((size_t)(row0 + fr) * K) * 2;
    const char* gBh = (const char*)g.Bhi + ((size_t)(col0 + fr) * K) * 2;
    const char* gBl = (const char*)g.Blo + ((size_t)(col0 + fr) * K) * 2;

    float c[2][8][4];
    #pragma unroll
    for (int mt = 0; mt < 2; mt++)
        #pragma unroll
        for (int nt = 0; nt < 8; nt++)
            #pragma unroll
            for (int i = 0; i < 4; i++) c[mt][nt][i] = 0.f;

    const int arow = wr * 32 + (lane & 7) + (lane & 8);
    const int acs  = (lane & 16) ? 1 : 0;
    const int brow0 = wc * 64 + (lane & 7) + ((lane & 16) ? 8 : 0);
    const int bcs   = (lane & 8) ? 1 : 0;

    {   // prologue: tile 0 -> stage 0
        #pragma unroll
        for (int c2 = 0; c2 < 2; c2++) {
            int cc = fc0 + c2;
            uint32_t so = swz(fr, cc);
            size_t go = cc * 16;
            CP16(sb + S_AHI + so, gA  + go);
            CP16(sb + S_BHI + so, gBh + go);
            CP16(sb + S_BLO + so, gBl + go);
        }
        CP_COMMIT();
    }

    for (int t = 0; t < nT; t++) {
        const int st = (t & 1) * STG;
        if (t + 1 < nT) {
            const int sn = ((t + 1) & 1) * STG;
            const size_t kb = (size_t)(t + 1) * 64;
            #pragma unroll
            for (int c2 = 0; c2 < 2; c2++) {
                int cc = fc0 + c2;
                uint32_t so = swz(fr, cc);
                size_t go = kb + cc * 16;
                CP16(sb + sn + S_AHI + so, gA  + go);
                CP16(sb + sn + S_BHI + so, gBh + go);
                CP16(sb + sn + S_BLO + so, gBl + go);
            }
            CP_COMMIT();
            CP_WAIT(1);
        } else {
            CP_WAIT(0);
        }
        __syncthreads();

        #pragma unroll
        for (int kk = 0; kk < 2; kk++) {
            uint32_t ah[2][4];
            #pragma unroll
            for (int mt = 0; mt < 2; mt++) {
                int r = arow + mt * 16;
                LDSM4(ah[mt], sb + st + S_AHI + swz(r, (kk << 1) + acs));
            }
            #pragma unroll
            for (int p = 0; p < 4; p++) {
                int r = brow0 + p * 16;
                uint32_t off = swz(r, (kk << 1) + bcs);
                uint32_t bh[4], bl[4];
                LDSM4(bh, sb + st + S_BHI + off);
                LDSM4(bl, sb + st + S_BLO + off);
                #pragma unroll
                for (int mt = 0; mt < 2; mt++) {
                    MMAH(c[mt][2 * p],     ah[mt], bh[0], bh[1]);
                    MMAH(c[mt][2 * p],     ah[mt], bl[0], bl[1]);
                    MMAH(c[mt][2 * p + 1], ah[mt], bh[2], bh[3]);
                    MMAH(c[mt][2 * p + 1], ah[mt], bl[2], bl[3]);
                }
            }
        }
        __syncthreads();
    }

    if (!g.fuse) {
        #pragma unroll
        for (int mt = 0; mt < 2; mt++) {
            int r = row0 + wr * 32 + mt * 16 + (lane >> 2);
            #pragma unroll
            for (int nt = 0; nt < 8; nt++) {
                int cc = col0 + wc * 64 + nt * 8 + 2 * (lane & 3);
                float b0 = g.bias ? g.bias[cc]     : 0.f;
                float b1 = g.bias ? g.bias[cc + 1] : 0.f;
                float v0 = c[mt][nt][0] + b0, v1 = c[mt][nt][1] + b1;
                float v2 = c[mt][nt][2] + b0, v3 = c[mt][nt][3] + b1;
                if (g.doRelu) {
                    v0 = fmaxf(v0, 0.f); v1 = fmaxf(v1, 0.f);
                    v2 = fmaxf(v2, 0.f); v3 = fmaxf(v3, 0.f);
                }
                *(float2*)&g.C[(size_t)r * g.ldc + cc]       = make_float2(v0, v1);
                *(float2*)&g.C[(size_t)(r + 8) * g.ldc + cc] = make_float2(v2, v3);
            }
        }
        return;
    }

    // ---- fused head epilogue ----
    float* Hs = (float*)smem;               // [128][HS_STRIDE]
    #pragma unroll
    for (int mt = 0; mt < 2; mt++) {
        int rl = wr * 32 + mt * 16 + (lane >> 2);
        #pragma unroll
        for (int nt = 0; nt < 8; nt++) {
            int cl = wc * 64 + nt * 8 + 2 * (lane & 3);
            float b0 = g.bias[col0 + cl], b1 = g.bias[col0 + cl + 1];
            float v0 = fmaxf(c[mt][nt][0] + b0, 0.f);
            float v1 = fmaxf(c[mt][nt][1] + b1, 0.f);
            float v2 = fmaxf(c[mt][nt][2] + b0, 0.f);
            float v3 = fmaxf(c[mt][nt][3] + b1, 0.f);
            *(float2*)&Hs[rl * HS_STRIDE + cl]       = make_float2(v0, v1);
            *(float2*)&Hs[(rl + 8) * HS_STRIDE + cl] = make_float2(v2, v3);
        }
    }
    __syncthreads();

    const int head = col0 >> 8;
    const int outd = (head == 0) ? 9 : (head == 1) ? 6 : 17;
    const size_t obase = (head == 0) ? 0 : (head == 1) ? 73728 : 122880;
    const float* W2p = g.W2 + (size_t)col0 * 32;

    const int rg = tid >> 3, cg = tid & 7;
    float acc[4][4];
    #pragma unroll
    for (int i = 0; i < 4; i++)
        #pragma unroll
        for (int j = 0; j < 4; j++) acc[i][j] = 0.f;

    #pragma unroll 4
    for (int k = 0; k < 128; k++) {
        float4 w = __ldg((const float4*)(W2p + (size_t)k * 32 + cg * 4));
        #pragma unroll
        for (int i = 0; i < 4; i++) {
            float hv = Hs[(rg * 4 + i) * HS_STRIDE + k];
            acc[i][0] = fmaf(hv, w.x, acc[i][0]);
            acc[i][1] = fmaf(hv, w.y, acc[i][1]);
            acc[i][2] = fmaf(hv, w.z, acc[i][2]);
            acc[i][3] = fmaf(hv, w.w, acc[i][3]);
        }
    }
    #pragma unroll
    for (int i = 0; i < 4; i++) {
        int row = row0 + rg * 4 + i;
        #pragma unroll
        for (int j = 0; j < 4; j++) {
            int cc = cg * 4 + j;
            if (cc < outd)
                atomicAdd(&g.outp[obase + (size_t)row * outd + cc], acc[i][j]);
        }
    }
}

// ---------------- fp16 helpers ----------------------------------------------
__device__ __forceinline__ void hsplit(float x, __half& hi, __half& lo) {
    hi = __float2half(x);
    lo = __float2half(x - __half2float(hi));
}
__device__ __forceinline__ uint32_t hpack(__half a, __half b) {
    __half2 t = __halves2half2(a, b);
    return *reinterpret_cast<uint32_t*>(&t);
}
__device__ __forceinline__ uint2 h4(float4 v) {
    uint2 r;
    r.x = hpack(__float2half(v.x), __float2half(v.y));
    r.y = hpack(__float2half(v.z), __float2half(v.w));
    return r;
}

// ---------------- pack_all ---------------------------------------------------
// grid: [0,256) wxw | [256,384) we | [384,1152) w1 + W2cat + b1cat.  256 thr.
__global__ void pack_all(const float* __restrict__ Wn,  const float* __restrict__ Wn2,
                         const float* __restrict__ We,  const float* __restrict__ We2,
                         const float* __restrict__ lrW1,  const float* __restrict__ lrb1,
                         const float* __restrict__ scrW1, const float* __restrict__ scrb1,
                         const float* __restrict__ mrW1,  const float* __restrict__ mrb1,
                         const float* __restrict__ lrW2,  const float* __restrict__ crW2,
                         const float* __restrict__ mrW2)
{
    int blk = blockIdx.x, t = threadIdx.x;
    if (blk < 256) {
        int n = blk;
        #pragma unroll
        for (int j = 0; j < 2; j++) {
            int k = t + j * 256;
            float v = (n < 128) ? Wn[k * 128 + n] : Wn2[k * 128 + (n - 128)];
            __half hi, lo; hsplit(v, hi, lo);
            d_WtXWhi[n * 512 + k] = hi; d_WtXWlo[n * 512 + k] = lo;
        }
    } else if (blk < 384) {
        int n = blk - 256, k = t;
        __half hi, lo;
        hsplit(We [k * 128 + n], hi, lo);
        d_WtEghi[n * 256 + k] = hi; d_WtEglo[n * 256 + k] = lo;
        hsplit(We2[k * 128 + n], hi, lo);
        d_WtQhi [n * 256 + k] = hi; d_WtQlo [n * 256 + k] = lo;
    } else {
        int n = blk - 384;
        const float* W; const float* bb; const float* W2; int cn, outd;
        if (n < 256)      { W = lrW1;  bb = lrb1;  W2 = lrW2; cn = n;       outd = 9;  }
        else if (n < 512) { W = scrW1; bb = scrb1; W2 = crW2; cn = n - 256; outd = 6;  }
        else              { W = mrW1;  bb = mrb1;  W2 = mrW2; cn = n - 512; outd = 17; }
        #pragma unroll
        for (int j = 0; j < 2; j++) {
            int k = t + j * 256;
            __half hi, lo; hsplit(W[k * 256 + cn], hi, lo);
            d_WtW1hi[n * 512 + k] = hi; d_WtW1lo[n * 512 + k] = lo;
        }
        if (t == 0) d_b1cat[n] = bb[cn];
        if (t < 32) d_W2cat[n * 32 + t] = (t < outd) ? W2[cn * outd + t] : 0.f;
    }
}

// ---------------- prep_all ---------------------------------------------------
// grid: [0,2048) maskX+aggzero | [2048,10240) gatherEg | [10240,14336) gatherEFp
//       | [14336,14848) out bias init.  128 thr.
__global__ void prep_all(const float* __restrict__ nf, const float* __restrict__ ef,
                         const int* __restrict__ ei, const int* __restrict__ pairs,
                         const int* __restrict__ num_obj, const int* __restrict__ num_edges,
                         const float* __restrict__ lrb2, const float* __restrict__ crb2,
                         const float* __restrict__ mrb2, float* __restrict__ out)
{
    int blk = blockIdx.x, t = threadIdx.x;
    if (blk < 2048) {
        int b = blk >> 7, n = blk & 127;
        float4 v = make_float4(0.f, 0.f, 0.f, 0.f);
        if (n < num_obj[b]) v = ((const float4*)nf)[(size_t)blk * 128 + t];
        ((uint2*)d_Xh)[(size_t)blk * 128 + t] = h4(v);
        d_agg[(size_t)blk * 128 + t] = 0.f;
    } else if (blk < 10240) {
        int idx = (blk - 2048) * 2 + (t >> 6);
        int b = idx >> 10, m = idx & 1023, tt = t & 63;
        float4 v = make_float4(0.f, 0.f, 0.f, 0.f);
        if (m < num_edges[b]) {
            int s = ei[b * 2048 + m];
            int d = ei[b * 2048 + 1024 + m];
            v = ((const float4*)ef)[(((size_t)b * 128 + s) * 128 + d) * 64 + tt];
        }
        ((uint2*)d_Egh)[(size_t)idx * 64 + tt] = h4(v);
    } else if (blk < 14336) {
        int idx = (blk - 10240) * 2 + (t >> 6);
        int b = idx / 512, tt = t & 63;
        int p0 = pairs[idx * 2], p1 = pairs[idx * 2 + 1];
        float4 v = ((const float4*)ef)[(((size_t)b * 128 + p0) * 128 + p1) * 64 + tt];
        ((uint2*)d_EFph)[(size_t)idx * 64 + tt] = h4(v);
    } else {
        int base = (blk - 14336) * 512 + t * 4;
        #pragma unroll
        for (int j = 0; j < 4; j++) {
            int i = base + j;
            float v;
            if (i < 73728)       v = lrb2[i % 9];
            else if (i < 122880) v = crb2[(i - 73728) % 6];
            else                 v = mrb2[(i - 122880) % 17];
            out[i] = v;
        }
    }
}

// ---------------- graph_all: adj conv + line conv (+fused src scatter) -------
// grid: [0,2048) adj_h | [2048,18432) line conv.  128 thr.
__global__ void graph_all(const float* __restrict__ adj, const float* __restrict__ ladj,
                          const int* __restrict__ ei,
                          const int* __restrict__ num_obj, const int* __restrict__ num_edges)
{
    __shared__ int   s_jidx[1024];
    __shared__ float s_jw[1024];
    __shared__ int   s_cnt;

    int blk = blockIdx.x, t = threadIdx.x;
    if (blk < 2048) {
        int b = blk >> 7, i = blk & 127;
        int no = num_obj[b];
        float* outp = &d_h[(size_t)blk * 128];
        if (i >= no) { outp[t] = 0.f; return; }
        s_jw[t] = adj[(size_t)blk * 128 + t];
        __syncthreads();
        const float* xw = &d_XWp[(size_t)b * 128 * 256];
        float acc = xw[i * 256 + t];
        for (int j = 0; j < no; ++j) {
            float w = s_jw[j];
            if (w != 0.f) acc = fmaf(w, xw[j * 256 + t], acc);
        }
        outp[t] = fmaxf(acc, 0.f);
    } else {
        int lb = blk - 2048;
        int b = lb >> 10, m = lb & 1023;
        int ne = num_edges[b];
        if (m >= ne) return;
        if (t == 0) s_cnt = 0;
        __syncthreads();
        // scan L row directly from global, compact nonzeros
        const float4* lp4 = (const float4*)(ladj + (size_t)lb * 1024);
        #pragma unroll
        for (int it = 0; it < 2; it++) {
            int j4 = t + it * 128;
            float4 w4 = lp4[j4];
            int jb = j4 * 4;
            if (w4.x != 0.f && jb     < ne) { int p = atomicAdd(&s_cnt, 1); s_jidx[p] = jb;     s_jw[p] = w4.x; }
            if (w4.y != 0.f && jb + 1 < ne) { int p = atomicAdd(&s_cnt, 1); s_jidx[p] = jb + 1; s_jw[p] = w4.y; }
            if (w4.z != 0.f && jb + 2 < ne) { int p = atomicAdd(&s_cnt, 1); s_jidx[p] = jb + 2; s_jw[p] = w4.z; }
            if (w4.w != 0.f && jb + 3 < ne) { int p = atomicAdd(&s_cnt, 1); s_jidx[p] = jb + 3; s_jw[p] = w4.w; }
        }
        __syncthreads();
        const float* ew = &d_EgWe[(size_t)b * 1024 * 128];
        float acc = ew[m * 128 + t];            // eye * emask term
        int c = s_cnt;
        for (int k = 0; k < c; ++k)
            acc = fmaf(s_jw[k], ew[s_jidx[k] * 128 + t], acc);
        acc = fmaxf(acc, 0.f);
        // fused scatter: agg[src[m]] += g[m]
        if (acc != 0.f) {
            int s = ei[b * 2048 + m];
            atomicAdd(&d_agg[((size_t)b * 128 + s) * 128 + t], acc);
        }
    }
}

__global__ void ci_kernel(const int* __restrict__ pairs,
                          const int* __restrict__ num_obj)
{
    int blk = blockIdx.x;                // 8192 blocks, 128 thr
    int b = blk / 512, t = threadIdx.x;
    int p0 = pairs[blk * 2], p1 = pairs[blk * 2 + 1];
    int no = num_obj[b];
    const float* hB = &d_h  [(size_t)b * 128 * 128];
    const float* aB = &d_agg[(size_t)b * 128 * 128];
    const float* xB = &d_XWp[(size_t)b * 128 * 256];
    float h0 = hB[p0 * 128 + t] + hB[p1 * 128 + t];
    float a0 = (p0 < no ? aB[p0 * 128 + t] : 0.f) +
               (p1 < no ? aB[p1 * 128 + t] : 0.f);
    float pm = fmaxf(xB[p0 * 256 + 128 + t] + xB[p1 * 256 + 128 + t], 0.f);
    float q  = d_Qp[(size_t)blk * 128 + t];
    size_t base = (size_t)blk * 512;
    d_CIh[base +       t] = __float2half(h0);
    d_CIh[base + 128 + t] = __float2half(a0);
    d_CIh[base + 256 + t] = __float2half(pm);
    d_CIh[base + 384 + t] = __float2half(q);
}

// ---------------- launch -----------------------------------------------------
extern "C" void kernel_launch(void* const* d_in, const int* in_sizes, int n_in,
                              void* d_out, int out_size)
{
    const float* nf    = (const float*)d_in[0];
    const float* ef    = (const float*)d_in[1];
    const float* adj   = (const float*)d_in[2];
    const float* ladj  = (const float*)d_in[3];
    const int*   ei    = (const int*)  d_in[4];
    const int*   pairs = (const int*)  d_in[5];
    const int*   nobj  = (const int*)  d_in[6];
    const int*   nedg  = (const int*)  d_in[7];
    const float* Wn    = (const float*)d_in[8];
    const float* We    = (const float*)d_in[9];
    const float* Wn2   = (const float*)d_in[10];
    const float* We2   = (const float*)d_in[11];
    const float* scrW1 = (const float*)d_in[12];
    const float* scrb1 = (const float*)d_in[13];
    const float* scrW2 = (const float*)d_in[14];
    const float* scrb2 = (const float*)d_in[15];
    const float* lrW1  = (const float*)d_in[16];
    const float* lrb1  = (const float*)d_in[17];
    const float* lrW2  = (const float*)d_in[18];
    const float* lrb2  = (const float*)d_in[19];
    const float* mrW1  = (const float*)d_in[20];
    const float* mrb1  = (const float*)d_in[21];
    const float* mrW2  = (const float*)d_in[22];
    const float* mrb2  = (const float*)d_in[23];
    float* out = (float*)d_out;

    cudaFuncSetAttribute(gemm_batch, cudaFuncAttributeMaxDynamicSharedMemorySize, GEMM_SMEM_MAX);

    __half *pXh, *pEgh, *pEFph, *pCIh;
    __half *pWtXWhi, *pWtXWlo, *pWtEghi, *pWtEglo, *pWtQhi, *pWtQlo, *pWtW1hi, *pWtW1lo;
    float *pXWp, *pEgWe, *pQp, *pb1, *pW2;
    cudaGetSymbolAddress((void**)&pXh,     d_Xh);
    cudaGetSymbolAddress((void**)&pEgh,    d_Egh);
    cudaGetSymbolAddress((void**)&pEFph,   d_EFph);
    cudaGetSymbolAddress((void**)&pCIh,    d_CIh);
    cudaGetSymbolAddress((void**)&pWtXWhi, d_WtXWhi);
    cudaGetSymbolAddress((void**)&pWtXWlo, d_WtXWlo);
    cudaGetSymbolAddress((void**)&pWtEghi, d_WtEghi);
    cudaGetSymbolAddress((void**)&pWtEglo, d_WtEglo);
    cudaGetSymbolAddress((void**)&pWtQhi,  d_WtQhi);
    cudaGetSymbolAddress((void**)&pWtQlo,  d_WtQlo);
    cudaGetSymbolAddress((void**)&pWtW1hi, d_WtW1hi);
    cudaGetSymbolAddress((void**)&pWtW1lo, d_WtW1lo);
    cudaGetSymbolAddress((void**)&pXWp,    d_XWp);
    cudaGetSymbolAddress((void**)&pEgWe,   d_EgWe);
    cudaGetSymbolAddress((void**)&pQp,     d_Qp);
    cudaGetSymbolAddress((void**)&pb1,     d_b1cat);
    cudaGetSymbolAddress((void**)&pW2,     d_W2cat);

    // 1. weight packing
    pack_all<<<1152, 256>>>(Wn, Wn2, We, We2, lrW1, lrb1, scrW1, scrb1,
                            mrW1, mrb1, lrW2, scrW2, mrW2);
    // 2. input prep + agg zero + out bias init
    prep_all<<<14848, 128>>>(nf, ef, ei, pairs, nobj, nedg, lrb2, scrb2, mrb2, out);
    // 3. batched GEMM: XWp (32) | EgWe (128) | Qp (64)
    {
        Gp gp;
        gp.n = 3;
        gp.d[0] = { pXh,   pWtXWhi, pWtXWlo, pXWp,  nullptr, nullptr, nullptr, 256, 512, 2,  32, 0, 0 };
        gp.d[1] = { pEgh,  pWtEghi, pWtEglo, pEgWe, nullptr, nullptr, nullptr, 128, 256, 1, 160, 0, 0 };
        gp.d[2] = { pEFph, pWtQhi,  pWtQlo,  pQp,   nullptr, nullptr, nullptr, 128, 256, 1, 224, 1, 0 };
        gemm_batch<<<224, 256, GEMM_SMEM_MAIN>>>(gp);
    }
    // 4. adj conv + line conv + fused src scatter
    graph_all<<<18432, 128>>>(adj, ladj, ei, nobj, nedg);
    // 5. classifier input assembly
    ci_kernel<<<8192, 128>>>(pairs, nobj);
    // 6. fused W1 GEMM + relu + heads -> out
    {
        Gp gp;
        gp.n = 1;
        gp.d[0] = { pCIh, pWtW1hi, pWtW1lo, nullptr, pb1, pW2, out, 768, 512, 6, 384, 1, 1 };
        gp.d[1] = gp.d[0];
        gp.d[2] = gp.d[0];
        gemm_batch<<<384, 256, GEMM_SMEM_FUSE>>>(gp);
    }
}

// round 9
// speedup vs baseline: 4.2426x; 1.1376x over previous
#include <cuda_runtime.h>
#include <cuda_fp16.h>
#include <cstdint>
#include <cstddef>

// Problem dims
#define BB   16
#define NN   128
#define MMx  1024
#define DNx  512
#define DEx  256
#define PPx  512

// ---------------- scratch (static __device__, no allocation) ----------------
__device__ __half d_Xh  [BB*NN*DNx];      // masked node feats fp16 (2048x512)
__device__ float  d_XWp [BB*NN*256];      // [XW|Xp]
__device__ float  d_h   [BB*NN*128];
__device__ __half d_Egh [BB*MMx*DEx];     // gathered edge feats    (16384x256)
__device__ float  d_EgWe[BB*MMx*128];
__device__ float  d_agg [BB*NN*128];
__device__ __half d_EFph[BB*PPx*DEx];     // edge feats at pairs    (8192x256)
__device__ float  d_Qp  [BB*PPx*128];
__device__ __half d_CIh [BB*PPx*512];     // classifier input       (8192x512)
// transposed + split weights: [N][K] K-major, fp16 hi/lo
__device__ __half d_WtXWhi[256*512], d_WtXWlo[256*512];
__device__ __half d_WtEghi[128*256], d_WtEglo[128*256];
__device__ __half d_WtQhi [128*256], d_WtQlo [128*256];
__device__ __half d_WtW1hi[768*512], d_WtW1lo[768*512];
__device__ float  d_b1cat[768];
__device__ __half d_W2Thi[32*768], d_W2Tlo[32*768];   // [outcol(pad32)][hidden]

// ---------------- asm helpers ------------------------------------------------
__device__ __forceinline__ uint32_t smem_u32(const void* p) {
    uint32_t a;
    asm("{ .reg .u64 t; cvta.to.shared.u64 t, %1; cvt.u32.u64 %0, t; }" : "=r"(a) : "l"(p));
    return a;
}
#define CP16(sa, ga) \
    asm volatile("cp.async.cg.shared.global [%0], [%1], 16;" :: "r"(sa), "l"(ga))
#define CP_COMMIT() asm volatile("cp.async.commit_group;" ::: "memory")
#define CP_WAIT(n)  asm volatile("cp.async.wait_group %0;" :: "n"(n) : "memory")

#define LDSM4(r, a) \
    asm volatile("ldmatrix.sync.aligned.m8n8.x4.shared.b16 {%0,%1,%2,%3}, [%4];" \
        : "=r"((r)[0]), "=r"((r)[1]), "=r"((r)[2]), "=r"((r)[3]) : "r"(a))

#define MMAH(c, a, b0, b1) \
    asm volatile("mma.sync.aligned.m16n8k16.row.col.f32.f16.f16.f32 " \
        "{%0,%1,%2,%3},{%4,%5,%6,%7},{%8,%9},{%0,%1,%2,%3};" \
        : "+f"((c)[0]), "+f"((c)[1]), "+f"((c)[2]), "+f"((c)[3]) \
        : "r"((a)[0]), "r"((a)[1]), "r"((a)[2]), "r"((a)[3]), "r"(b0), "r"(b1))

// ---------------- batched fp16 tensor-core GEMM ------------------------------
// C[M,N] = op(A @ B^T (+bias) (relu)); A fp16, B = Bhi+Blo fp16 (2-term).
// fuse=1: heads epilogue via MMA (H fp16 @ (W2hi+W2lo)), atomicAdd into out.
struct Gd {
    const __half *A, *Bhi, *Blo;
    float* C; const float* bias;
    const __half *W2hi, *W2lo; float* outp;
    int ldc, K, tilesX, blkEnd, doRelu, fuse;
};
struct Gp { Gd d[3]; int n; };

#define S_AHI 0
#define S_BHI 8192
#define S_BLO 16384
#define STG   24576
#define GEMM_SMEM  (2 * STG)               // 48 KB (also fuse: H 32K + W2 16K)
#define F_H    0
#define F_W2HI 32768
#define F_W2LO 40960

// swizzled byte offset of 16B chunk c (0..3) in row r (row = 64B)
__device__ __forceinline__ uint32_t swz(int r, int c) {
    return (uint32_t)(r * 64 + ((c ^ ((r >> 1) & 3)) << 4));
}
// swizzle for 256B rows (16 granules of 16B)
__device__ __forceinline__ uint32_t hswz(int r, int c) {
    return (uint32_t)(r * 256 + ((c ^ (r & 7)) << 4));
}

__device__ __forceinline__ uint32_t hpack(__half a, __half b) {
    __half2 t = __halves2half2(a, b);
    return *reinterpret_cast<uint32_t*>(&t);
}

__global__ __launch_bounds__(256, 2) void gemm_batch(Gp gp)
{
    extern __shared__ char smem[];
    const uint32_t sb = smem_u32(smem);

    int bid = blockIdx.x, di = 0;
    while (di < gp.n - 1 && bid >= gp.d[di].blkEnd) di++;
    const Gd g = gp.d[di];
    const int base  = di ? gp.d[di - 1].blkEnd : 0;
    const int local = bid - base;
    const int row0  = (local / g.tilesX) * 128;
    const int col0  = (local % g.tilesX) * 128;
    const int K     = g.K;
    const int nT    = K >> 5;

    const int tid = threadIdx.x, lane = tid & 31, wid = tid >> 5;
    const int wr = wid & 3, wc = wid >> 2;

    const int fr = tid >> 1, fc0 = (tid & 1) * 2;
    const char* gA  = (const char*)g.A   + ((size_t)(row0 + fr) * K) * 2;
    const char* gBh = (const char*)g.Bhi + ((size_t)(col0 + fr) * K) * 2;
    const char* gBl = (const char*)g.Blo + ((size_t)(col0 + fr) * K) * 2;

    float c[2][8][4];
    #pragma unroll
    for (int mt = 0; mt < 2; mt++)
        #pragma unroll
        for (int nt = 0; nt < 8; nt++)
            #pragma unroll
            for (int i = 0; i < 4; i++) c[mt][nt][i] = 0.f;

    const int arow = wr * 32 + (lane & 7) + (lane & 8);
    const int acs  = (lane & 16) ? 1 : 0;
    const int brow0 = wc * 64 + (lane & 7) + ((lane & 16) ? 8 : 0);
    const int bcs   = (lane & 8) ? 1 : 0;

    {   // prologue: tile 0 -> stage 0
        #pragma unroll
        for (int c2 = 0; c2 < 2; c2++) {
            int cc = fc0 + c2;
            uint32_t so = swz(fr, cc);
            size_t go = cc * 16;
            CP16(sb + S_AHI + so, gA  + go);
            CP16(sb + S_BHI + so, gBh + go);
            CP16(sb + S_BLO + so, gBl + go);
        }
        CP_COMMIT();
    }

    for (int t = 0; t < nT; t++) {
        const int st = (t & 1) * STG;
        if (t + 1 < nT) {
            const int sn = ((t + 1) & 1) * STG;
            const size_t kb = (size_t)(t + 1) * 64;
            #pragma unroll
            for (int c2 = 0; c2 < 2; c2++) {
                int cc = fc0 + c2;
                uint32_t so = swz(fr, cc);
                size_t go = kb + cc * 16;
                CP16(sb + sn + S_AHI + so, gA  + go);
                CP16(sb + sn + S_BHI + so, gBh + go);
                CP16(sb + sn + S_BLO + so, gBl + go);
            }
            CP_COMMIT();
            CP_WAIT(1);
        } else {
            CP_WAIT(0);
        }
        __syncthreads();

        #pragma unroll
        for (int kk = 0; kk < 2; kk++) {
            uint32_t ah[2][4];
            #pragma unroll
            for (int mt = 0; mt < 2; mt++) {
                int r = arow + mt * 16;
                LDSM4(ah[mt], sb + st + S_AHI + swz(r, (kk << 1) + acs));
            }
            #pragma unroll
            for (int p = 0; p < 4; p++) {
                int r = brow0 + p * 16;
                uint32_t off = swz(r, (kk << 1) + bcs);
                uint32_t bh[4], bl[4];
                LDSM4(bh, sb + st + S_BHI + off);
                LDSM4(bl, sb + st + S_BLO + off);
                #pragma unroll
                for (int mt = 0; mt < 2; mt++) {
                    MMAH(c[mt][2 * p],     ah[mt], bh[0], bh[1]);
                    MMAH(c[mt][2 * p],     ah[mt], bl[0], bl[1]);
                    MMAH(c[mt][2 * p + 1], ah[mt], bh[2], bh[3]);
                    MMAH(c[mt][2 * p + 1], ah[mt], bl[2], bl[3]);
                }
            }
        }
        __syncthreads();
    }

    if (!g.fuse) {
        #pragma unroll
        for (int mt = 0; mt < 2; mt++) {
            int r = row0 + wr * 32 + mt * 16 + (lane >> 2);
            #pragma unroll
            for (int nt = 0; nt < 8; nt++) {
                int cc = col0 + wc * 64 + nt * 8 + 2 * (lane & 3);
                float b0 = g.bias ? g.bias[cc]     : 0.f;
                float b1 = g.bias ? g.bias[cc + 1] : 0.f;
                float v0 = c[mt][nt][0] + b0, v1 = c[mt][nt][1] + b1;
                float v2 = c[mt][nt][2] + b0, v3 = c[mt][nt][3] + b1;
                if (g.doRelu) {
                    v0 = fmaxf(v0, 0.f); v1 = fmaxf(v1, 0.f);
                    v2 = fmaxf(v2, 0.f); v3 = fmaxf(v3, 0.f);
                }
                *(float2*)&g.C[(size_t)r * g.ldc + cc]       = make_float2(v0, v1);
                *(float2*)&g.C[(size_t)(r + 8) * g.ldc + cc] = make_float2(v2, v3);
            }
        }
        return;
    }

    // ---- fused head epilogue (tensor-core): H fp16 -> smem; cp.async W2 ----
    #pragma unroll
    for (int mt = 0; mt < 2; mt++) {
        int rl = wr * 32 + mt * 16 + (lane >> 2);
        #pragma unroll
        for (int nt = 0; nt < 8; nt++) {
            int cl = wc * 64 + nt * 8 + 2 * (lane & 3);
            float b0 = g.bias[col0 + cl], b1 = g.bias[col0 + cl + 1];
            float v0 = fmaxf(c[mt][nt][0] + b0, 0.f);
            float v1 = fmaxf(c[mt][nt][1] + b1, 0.f);
            float v2 = fmaxf(c[mt][nt][2] + b0, 0.f);
            float v3 = fmaxf(c[mt][nt][3] + b1, 0.f);
            uint32_t go = ((cl >> 3) ^ 0) ;
            (void)go;
            *(uint32_t*)(smem + F_H + hswz(rl,     cl >> 3) + (cl & 7) * 2) =
                hpack(__float2half(v0), __float2half(v1));
            *(uint32_t*)(smem + F_H + hswz(rl + 8, cl >> 3) + (cl & 7) * 2) =
                hpack(__float2half(v2), __float2half(v3));
        }
    }
    {   // W2 slices: rows j 0..31, k = col0..col0+127
        int j = tid >> 3, c8 = tid & 7;
        #pragma unroll
        for (int half = 0; half < 2; half++) {
            int c16 = c8 + half * 8;
            size_t so = ((size_t)j * 768 + col0 + c16 * 8) * 2;
            CP16(sb + F_W2HI + hswz(j, c16), (const char*)g.W2hi + so);
            CP16(sb + F_W2LO + hswz(j, c16), (const char*)g.W2lo + so);
        }
        CP_COMMIT(); CP_WAIT(0);
    }
    __syncthreads();

    const int head = col0 >> 8;
    const int outd = (head == 0) ? 9 : (head == 1) ? 6 : 17;
    const size_t obase = (head == 0) ? 0 : (head == 1) ? 73728 : 122880;

    const int wm = wid * 16;
    float cN[4][4];
    #pragma unroll
    for (int i = 0; i < 4; i++)
        #pragma unroll
        for (int j = 0; j < 4; j++) cN[i][j] = 0.f;

    const int harow = wm + (lane & 7) + (lane & 8);
    const int hacs  = (lane & 16) ? 1 : 0;
    const int wbr   = (lane & 7) + ((lane & 16) ? 8 : 0);
    const int wbcs  = (lane & 8) ? 1 : 0;

    #pragma unroll
    for (int ks = 0; ks < 8; ks++) {
        uint32_t a[4];
        LDSM4(a, sb + F_H + hswz(harow, 2 * ks + hacs));
        #pragma unroll
        for (int nb = 0; nb < 2; nb++) {
            uint32_t off = hswz(nb * 16 + wbr, 2 * ks + wbcs);
            uint32_t bh[4], bl[4];
            LDSM4(bh, sb + F_W2HI + off);
            LDSM4(bl, sb + F_W2LO + off);
            MMAH(cN[2 * nb],     a, bh[0], bh[1]);
            MMAH(cN[2 * nb],     a, bl[0], bl[1]);
            MMAH(cN[2 * nb + 1], a, bh[2], bh[3]);
            MMAH(cN[2 * nb + 1], a, bl[2], bl[3]);
        }
    }
    #pragma unroll
    for (int ns = 0; ns < 4; ns++) {
        int col = ns * 8 + 2 * (lane & 3);
        int r0 = row0 + wm + (lane >> 2);
        if (col < outd) {
            atomicAdd(&g.outp[obase + (size_t)r0 * outd + col],       cN[ns][0]);
            atomicAdd(&g.outp[obase + (size_t)(r0 + 8) * outd + col], cN[ns][2]);
        }
        if (col + 1 < outd) {
            atomicAdd(&g.outp[obase + (size_t)r0 * outd + col + 1],       cN[ns][1]);
            atomicAdd(&g.outp[obase + (size_t)(r0 + 8) * outd + col + 1], cN[ns][3]);
        }
    }
}

// ---------------- fp16 helpers ----------------------------------------------
__device__ __forceinline__ void hsplit(float x, __half& hi, __half& lo) {
    hi = __float2half(x);
    lo = __float2half(x - __half2float(hi));
}
__device__ __forceinline__ uint2 h4(float4 v) {
    uint2 r;
    r.x = hpack(__float2half(v.x), __float2half(v.y));
    r.y = hpack(__float2half(v.z), __float2half(v.w));
    return r;
}

// ---------------- setup_all: weight packing + input prep ---------------------
// grid (256 thr): [0,1152) pack | [1152,2176) maskX+aggzero | [2176,6272) Eg
//                 [6272,8320) EFp | [8320,8576) out bias init
__global__ void setup_all(const float* __restrict__ nf, const float* __restrict__ ef,
                          const int* __restrict__ ei, const int* __restrict__ pairs,
                          const int* __restrict__ num_obj, const int* __restrict__ num_edges,
                          const float* __restrict__ Wn,  const float* __restrict__ Wn2,
                          const float* __restrict__ We,  const float* __restrict__ We2,
                          const float* __restrict__ lrW1,  const float* __restrict__ lrb1,
                          const float* __restrict__ scrW1, const float* __restrict__ scrb1,
                          const float* __restrict__ mrW1,  const float* __restrict__ mrb1,
                          const float* __restrict__ lrW2,  const float* __restrict__ crW2,
                          const float* __restrict__ mrW2,
                          const float* __restrict__ lrb2,  const float* __restrict__ crb2,
                          const float* __restrict__ mrb2,  float* __restrict__ out)
{
    int blk = blockIdx.x, t = threadIdx.x;
    if (blk < 1152) {
        if (blk < 256) {
            int n = blk;
            #pragma unroll
            for (int j = 0; j < 2; j++) {
                int k = t + j * 256;
                float v = (n < 128) ? Wn[k * 128 + n] : Wn2[k * 128 + (n - 128)];
                __half hi, lo; hsplit(v, hi, lo);
                d_WtXWhi[n * 512 + k] = hi; d_WtXWlo[n * 512 + k] = lo;
            }
        } else if (blk < 384) {
            int n = blk - 256, k = t;
            __half hi, lo;
            hsplit(We [k * 128 + n], hi, lo);
            d_WtEghi[n * 256 + k] = hi; d_WtEglo[n * 256 + k] = lo;
            hsplit(We2[k * 128 + n], hi, lo);
            d_WtQhi [n * 256 + k] = hi; d_WtQlo [n * 256 + k] = lo;
        } else {
            int n = blk - 384;
            const float* W; const float* bb; const float* W2; int cn, outd;
            if (n < 256)      { W = lrW1;  bb = lrb1;  W2 = lrW2; cn = n;       outd = 9;  }
            else if (n < 512) { W = scrW1; bb = scrb1; W2 = crW2; cn = n - 256; outd = 6;  }
            else              { W = mrW1;  bb = mrb1;  W2 = mrW2; cn = n - 512; outd = 17; }
            #pragma unroll
            for (int j = 0; j < 2; j++) {
                int k = t + j * 256;
                __half hi, lo; hsplit(W[k * 256 + cn], hi, lo);
                d_WtW1hi[n * 512 + k] = hi; d_WtW1lo[n * 512 + k] = lo;
            }
            if (t == 0) d_b1cat[n] = bb[cn];
            if (t < 32) {
                float v = (t < outd) ? W2[cn * outd + t] : 0.f;
                __half hi, lo; hsplit(v, hi, lo);
                d_W2Thi[t * 768 + n] = hi; d_W2Tlo[t * 768 + n] = lo;
            }
        }
    } else if (blk < 2176) {
        int idx = (blk - 1152) * 2 + (t >> 7);       // 0..2047
        int b = idx >> 7, n = idx & 127, tt = t & 127;
        float4 v = make_float4(0.f, 0.f, 0.f, 0.f);
        if (n < num_obj[b]) v = ((const float4*)nf)[(size_t)idx * 128 + tt];
        ((uint2*)d_Xh)[(size_t)idx * 128 + tt] = h4(v);
        d_agg[(size_t)idx * 128 + tt] = 0.f;
    } else if (blk < 6272) {
        int idx = (blk - 2176) * 4 + (t >> 6);       // 0..16383
        int b = idx >> 10, m = idx & 1023, tt = t & 63;
        float4 v = make_float4(0.f, 0.f, 0.f, 0.f);
        if (m < num_edges[b]) {
            int s = ei[b * 2048 + m];
            int d = ei[b * 2048 + 1024 + m];
            v = ((const float4*)ef)[(((size_t)b * 128 + s) * 128 + d) * 64 + tt];
        }
        ((uint2*)d_Egh)[(size_t)idx * 64 + tt] = h4(v);
    } else if (blk < 8320) {
        int idx = (blk - 6272) * 4 + (t >> 6);       // 0..8191
        int b = idx / 512, tt = t & 63;
        int p0 = pairs[idx * 2], p1 = pairs[idx * 2 + 1];
        float4 v = ((const float4*)ef)[(((size_t)b * 128 + p0) * 128 + p1) * 64 + tt];
        ((uint2*)d_EFph)[(size_t)idx * 64 + tt] = h4(v);
    } else {
        int basei = (blk - 8320) * 1024 + t * 4;     // 262144 total
        #pragma unroll
        for (int j = 0; j < 4; j++) {
            int i = basei + j;
            float v;
            if (i < 73728)       v = lrb2[i % 9];
            else if (i < 122880) v = crb2[(i - 73728) % 6];
            else                 v = mrb2[(i - 122880) % 17];
            out[i] = v;
        }
    }
}

// ---------------- graph_all: adj conv + line conv (+fused src scatter) -------
// grid: [0,2048) adj_h | [2048,18432) line conv.  128 thr.
__global__ void graph_all(const float* __restrict__ adj, const float* __restrict__ ladj,
                          const int* __restrict__ ei,
                          const int* __restrict__ num_obj, const int* __restrict__ num_edges)
{
    __shared__ int   s_jidx[1024];
    __shared__ float s_jw[1024];
    __shared__ int   s_cnt;

    int blk = blockIdx.x, t = threadIdx.x;
    if (blk < 2048) {
        int b = blk >> 7, i = blk & 127;
        int no = num_obj[b];
        float* outp = &d_h[(size_t)blk * 128];
        if (i >= no) { outp[t] = 0.f; return; }
        if (t == 0) s_cnt = 0;
        __syncthreads();
        float w = adj[(size_t)blk * 128 + t];
        if (t < no && w != 0.f) { int p = atomicAdd(&s_cnt, 1); s_jidx[p] = t; s_jw[p] = w; }
        __syncthreads();
        const float* xw = &d_XWp[(size_t)b * 128 * 256];
        float a0 = xw[i * 256 + t], a1 = 0.f;       // eye term
        int c = s_cnt, k = 0;
        for (; k + 1 < c; k += 2) {
            a0 = fmaf(s_jw[k],     xw[s_jidx[k] * 256 + t],     a0);
            a1 = fmaf(s_jw[k + 1], xw[s_jidx[k + 1] * 256 + t], a1);
        }
        if (k < c) a0 = fmaf(s_jw[k], xw[s_jidx[k] * 256 + t], a0);
        outp[t] = fmaxf(a0 + a1, 0.f);
    } else {
        int lb = blk - 2048;
        int b = lb >> 10, m = lb & 1023;
        int ne = num_edges[b];
        if (m >= ne) return;
        if (t == 0) s_cnt = 0;
        __syncthreads();
        const float4* lp4 = (const float4*)(ladj + (size_t)lb * 1024);
        #pragma unroll
        for (int it = 0; it < 2; it++) {
            int j4 = t + it * 128;
            float4 w4 = lp4[j4];
            int jb = j4 * 4;
            if (w4.x != 0.f && jb     < ne) { int p = atomicAdd(&s_cnt, 1); s_jidx[p] = jb;     s_jw[p] = w4.x; }
            if (w4.y != 0.f && jb + 1 < ne) { int p = atomicAdd(&s_cnt, 1); s_jidx[p] = jb + 1; s_jw[p] = w4.y; }
            if (w4.z != 0.f && jb + 2 < ne) { int p = atomicAdd(&s_cnt, 1); s_jidx[p] = jb + 2; s_jw[p] = w4.z; }
            if (w4.w != 0.f && jb + 3 < ne) { int p = atomicAdd(&s_cnt, 1); s_jidx[p] = jb + 3; s_jw[p] = w4.w; }
        }
        __syncthreads();
        const float* ew = &d_EgWe[(size_t)b * 1024 * 128];
        float a0 = ew[m * 128 + t], a1 = 0.f;       // eye * emask term
        int c = s_cnt, k = 0;
        for (; k + 1 < c; k += 2) {
            a0 = fmaf(s_jw[k],     ew[s_jidx[k] * 128 + t],     a0);
            a1 = fmaf(s_jw[k + 1], ew[s_jidx[k + 1] * 128 + t], a1);
        }
        if (k < c) a0 = fmaf(s_jw[k], ew[s_jidx[k] * 128 + t], a0);
        float acc = fmaxf(a0 + a1, 0.f);
        if (acc != 0.f) {
            int s = ei[b * 2048 + m];
            atomicAdd(&d_agg[((size_t)b * 128 + s) * 128 + t], acc);
        }
    }
}

__global__ void ci_kernel(const int* __restrict__ pairs,
                          const int* __restrict__ num_obj)
{
    int blk = blockIdx.x;                // 8192 blocks, 128 thr
    int b = blk / 512, t = threadIdx.x;
    int p0 = pairs[blk * 2], p1 = pairs[blk * 2 + 1];
    int no = num_obj[b];
    const float* hB = &d_h  [(size_t)b * 128 * 128];
    const float* aB = &d_agg[(size_t)b * 128 * 128];
    const float* xB = &d_XWp[(size_t)b * 128 * 256];
    float h0 = hB[p0 * 128 + t] + hB[p1 * 128 + t];
    float a0 = (p0 < no ? aB[p0 * 128 + t] : 0.f) +
               (p1 < no ? aB[p1 * 128 + t] : 0.f);
    float pm = fmaxf(xB[p0 * 256 + 128 + t] + xB[p1 * 256 + 128 + t], 0.f);
    float q  = d_Qp[(size_t)blk * 128 + t];
    size_t base = (size_t)blk * 512;
    d_CIh[base +       t] = __float2half(h0);
    d_CIh[base + 128 + t] = __float2half(a0);
    d_CIh[base + 256 + t] = __float2half(pm);
    d_CIh[base + 384 + t] = __float2half(q);
}

// ---------------- launch -----------------------------------------------------
extern "C" void kernel_launch(void* const* d_in, const int* in_sizes, int n_in,
                              void* d_out, int out_size)
{
    const float* nf    = (const float*)d_in[0];
    const float* ef    = (const float*)d_in[1];
    const float* adj   = (const float*)d_in[2];
    const float* ladj  = (const float*)d_in[3];
    const int*   ei    = (const int*)  d_in[4];
    const int*   pairs = (const int*)  d_in[5];
    const int*   nobj  = (const int*)  d_in[6];
    const int*   nedg  = (const int*)  d_in[7];
    const float* Wn    = (const float*)d_in[8];
    const float* We    = (const float*)d_in[9];
    const float* Wn2   = (const float*)d_in[10];
    const float* We2   = (const float*)d_in[11];
    const float* scrW1 = (const float*)d_in[12];
    const float* scrb1 = (const float*)d_in[13];
    const float* scrW2 = (const float*)d_in[14];
    const float* scrb2 = (const float*)d_in[15];
    const float* lrW1  = (const float*)d_in[16];
    const float* lrb1  = (const float*)d_in[17];
    const float* lrW2  = (const float*)d_in[18];
    const float* lrb2  = (const float*)d_in[19];
    const float* mrW1  = (const float*)d_in[20];
    const float* mrb1  = (const float*)d_in[21];
    const float* mrW2  = (const float*)d_in[22];
    const float* mrb2  = (const float*)d_in[23];
    float* out = (float*)d_out;

    cudaFuncSetAttribute(gemm_batch, cudaFuncAttributeMaxDynamicSharedMemorySize, GEMM_SMEM);

    __half *pXh, *pEgh, *pEFph, *pCIh;
    __half *pWtXWhi, *pWtXWlo, *pWtEghi, *pWtEglo, *pWtQhi, *pWtQlo, *pWtW1hi, *pWtW1lo;
    __half *pW2hi, *pW2lo;
    float *pXWp, *pEgWe, *pQp, *pb1;
    cudaGetSymbolAddress((void**)&pXh,     d_Xh);
    cudaGetSymbolAddress((void**)&pEgh,    d_Egh);
    cudaGetSymbolAddress((void**)&pEFph,   d_EFph);
    cudaGetSymbolAddress((void**)&pCIh,    d_CIh);
    cudaGetSymbolAddress((void**)&pWtXWhi, d_WtXWhi);
    cudaGetSymbolAddress((void**)&pWtXWlo, d_WtXWlo);
    cudaGetSymbolAddress((void**)&pWtEghi, d_WtEghi);
    cudaGetSymbolAddress((void**)&pWtEglo, d_WtEglo);
    cudaGetSymbolAddress((void**)&pWtQhi,  d_WtQhi);
    cudaGetSymbolAddress((void**)&pWtQlo,  d_WtQlo);
    cudaGetSymbolAddress((void**)&pWtW1hi, d_WtW1hi);
    cudaGetSymbolAddress((void**)&pWtW1lo, d_WtW1lo);
    cudaGetSymbolAddress((void**)&pW2hi,   d_W2Thi);
    cudaGetSymbolAddress((void**)&pW2lo,   d_W2Tlo);
    cudaGetSymbolAddress((void**)&pXWp,    d_XWp);
    cudaGetSymbolAddress((void**)&pEgWe,   d_EgWe);
    cudaGetSymbolAddress((void**)&pQp,     d_Qp);
    cudaGetSymbolAddress((void**)&pb1,     d_b1cat);

    // 1. weight packing + input prep + agg zero + out bias init
    setup_all<<<8576, 256>>>(nf, ef, ei, pairs, nobj, nedg,
                             Wn, Wn2, We, We2, lrW1, lrb1, scrW1, scrb1,
                             mrW1, mrb1, lrW2, scrW2, mrW2, lrb2, scrb2, mrb2, out);
    // 2. batched GEMM: XWp (32) | EgWe (128) | Qp (64)
    {
        Gp gp;
        gp.n = 3;
        gp.d[0] = { pXh,   pWtXWhi, pWtXWlo, pXWp,  nullptr, nullptr, nullptr, nullptr, 256, 512, 2,  32, 0, 0 };
        gp.d[1] = { pEgh,  pWtEghi, pWtEglo, pEgWe, nullptr, nullptr, nullptr, nullptr, 128, 256, 1, 160, 0, 0 };
        gp.d[2] = { pEFph, pWtQhi,  pWtQlo,  pQp,   nullptr, nullptr, nullptr, nullptr, 128, 256, 1, 224, 1, 0 };
        gemm_batch<<<224, 256, GEMM_SMEM>>>(gp);
    }
    // 3. adj conv + line conv + fused src scatter
    graph_all<<<18432, 128>>>(adj, ladj, ei, nobj, nedg);
    // 4. classifier input assembly
    ci_kernel<<<8192, 128>>>(pairs, nobj);
    // 5. fused W1 GEMM + relu + tensor-core heads -> out
    {
        Gp gp;
        gp.n = 1;
        gp.d[0] = { pCIh, pWtW1hi, pWtW1lo, nullptr, pb1, pW2hi, pW2lo, out, 768, 512, 6, 384, 1, 1 };
        gp.d[1] = gp.d[0];
        gp.d[2] = gp.d[0];
        gemm_batch<<<384, 256, GEMM_SMEM>>>(gp);
    }
}